// round 11
// baseline (speedup 1.0000x reference)
#include <cuda_runtime.h>
#include <cuda_bf16.h>
#include <math.h>
#include <stdint.h>

// ---------------- problem constants ----------------
#define T_TOK   1024
#define D_DIM   2048
#define DFF_DIM 1024
#define E_EXP   16
#define K_TOP   6
#define P_PAIR  (T_TOK * K_TOP)          // 6144
#define BM      128
#define P_PAD   (P_PAIR + E_EXP * BM)    // 8192
#define MAX_TILES (P_PAD / BM)           // 64
#define KBLK    16

// smem stage: A planes 128 rows, B planes 64 rows, 80B row stride (conflict-free)
#define ROWSTRIDE 80
#define A_HI 0
#define A_LO 10240
#define B_HI 20480
#define B_LO 25600
#define STAGE1 30720
#define SMEM_BYTES (2 * STAGE1)          // 61440, double buffered; 3 CTA/SM = 184KB

// ---------------- static device scratch ----------------
__device__ int   g_rows[P_PAD];
__device__ int   g_slot[P_PAIR];
__device__ int   g_cnt [E_EXP];
__device__ int   g_cur [E_EXP];
__device__ int   g_tile_e[MAX_TILES];
__device__ int   g_ntiles;
__device__ int   g_sel64;
__device__ __nv_bfloat16 g_Hhi[(size_t)P_PAD * DFF_DIM];   // 16 MB
__device__ __nv_bfloat16 g_Hlo[(size_t)P_PAD * DFF_DIM];   // 16 MB
__device__ float         g_Y  [(size_t)P_PAD * D_DIM];     // 64 MB

// ---------------- helpers ----------------
__device__ __forceinline__ uint32_t smem_u32(const void* p) {
    uint32_t a;
    asm("{ .reg .u64 t; cvta.to.shared.u64 t, %1; cvt.u32.u64 %0, t; }" : "=r"(a) : "l"(p));
    return a;
}

#define LDSM4(r, addr)                                                        \
    asm volatile("ldmatrix.sync.aligned.m8n8.x4.shared.b16 {%0,%1,%2,%3}, [%4];" \
        : "=r"((r)[0]), "=r"((r)[1]), "=r"((r)[2]), "=r"((r)[3]) : "r"(addr))

#define MMA(c, a, b0, b1)                                                     \
    asm volatile("mma.sync.aligned.m16n8k16.row.col.f32.bf16.bf16.f32 "       \
        "{%0,%1,%2,%3}, {%4,%5,%6,%7}, {%8,%9}, {%0,%1,%2,%3};"               \
        : "+f"((c)[0]), "+f"((c)[1]), "+f"((c)[2]), "+f"((c)[3])              \
        : "r"((a)[0]), "r"((a)[1]), "r"((a)[2]), "r"((a)[3]), "r"(b0), "r"(b1))

// fp32x4 -> bf16 hi (uint2) + bf16 lo (uint2); error-free split
__device__ __forceinline__ void cvt4(float4 v, uint2& hh, uint2& ll) {
    float f[4] = {v.x, v.y, v.z, v.w};
    uint32_t h[4], l[4];
    #pragma unroll
    for (int i = 0; i < 4; i++) {
        __nv_bfloat16 bh = __float2bfloat16(f[i]);
        __nv_bfloat16 bl = __float2bfloat16(f[i] - __bfloat162float(bh));
        h[i] = (uint32_t)__bfloat16_as_ushort(bh);
        l[i] = (uint32_t)__bfloat16_as_ushort(bl);
    }
    hh = make_uint2(h[0] | (h[1] << 16), h[2] | (h[3] << 16));
    ll = make_uint2(l[0] | (l[1] << 16), l[2] | (l[3] << 16));
}

// ---------------- prep0: init scratch + dtype detection ----------------
__global__ void prep0_kernel(const void* sel) {
    int i = blockIdx.x * blockDim.x + threadIdx.x;
    if (i < P_PAD) g_rows[i] = -1;
    if (i < E_EXP) { g_cnt[i] = 0; g_cur[i] = 0; }
    if (blockIdx.x == 0) {
        __shared__ int bad;
        if (threadIdx.x == 0) bad = 0;
        __syncthreads();
        const int* w = (const int*)sel;
        for (int j = threadIdx.x; j < 1024; j += blockDim.x) {
            int lo = w[2 * j], hi = w[2 * j + 1];
            if (hi != 0 || (unsigned)lo >= E_EXP) atomicOr(&bad, 1);
        }
        __syncthreads();
        if (threadIdx.x == 0) g_sel64 = bad ? 0 : 1;
    }
}
__device__ __forceinline__ int load_expert(const void* sel, int p) {
    int e = g_sel64 ? (int)((const long long*)sel)[p] : ((const int*)sel)[p];
    return e & (E_EXP - 1);
}

__global__ void count_kernel(const void* __restrict__ sel) {
    int p = blockIdx.x * blockDim.x + threadIdx.x;
    if (p < P_PAIR) atomicAdd(&g_cnt[load_expert(sel, p)], 1);
}

__global__ void setup_fill_kernel(const void* __restrict__ sel) {
    __shared__ int basepad[E_EXP];
    if (threadIdx.x == 0) {
        int pos = 0;
        for (int e = 0; e < E_EXP; e++) {
            basepad[e] = pos;
            int tiles = (g_cnt[e] + BM - 1) / BM;
            for (int i = 0; i < tiles; i++) g_tile_e[pos / BM + i] = e;
            pos += tiles * BM;
        }
        g_ntiles = pos / BM;
    }
    __syncthreads();
    for (int p = threadIdx.x; p < P_PAIR; p += blockDim.x) {
        int e = load_expert(sel, p);
        int idx = basepad[e] + atomicAdd(&g_cur[e], 1);
        g_rows[idx] = p / K_TOP;
        g_slot[p] = idx;
    }
}

// ---------------- GEMM1: x @ [w0|w1 interleaved]^T -> SwiGLU -> H ----------------
// CTA 128 rows x 64 interleaved n (= 32 dff cols). Warp grid 4x2, warp tile 32x32.
// KBLK=16: one k16 slice per stage, 3 CTAs/SM.
__global__ void __launch_bounds__(256, 3) gemm1_mma(
    const float* __restrict__ x,  const float* __restrict__ w0,
    const float* __restrict__ w1, const float* __restrict__ s0,
    const float* __restrict__ s1)
{
    int tile = blockIdx.y;
    if (tile >= g_ntiles) return;
    int e  = g_tile_e[tile];
    int bx = blockIdx.x;

    extern __shared__ char smem[];
    uint32_t sb = smem_u32(smem);
    int tid = threadIdx.x, lane = tid & 31, wid = tid >> 5;
    int wr = wid >> 1, wc = wid & 1;

    // ---- A fill: 512 float4 over 256 threads (2 each), coalesced ----
    const float* axp[2];
    uint32_t stsAoff[2];
    #pragma unroll
    for (int i = 0; i < 2; i++) {
        int idx = i * 256 + tid;
        int row = idx >> 2, slot = idx & 3;        // row 0..127, slot 0..3 (float4)
        int grow = g_rows[tile * BM + row];
        axp[i] = (grow >= 0) ? x + (size_t)grow * D_DIM + slot * 4 : (const float*)0;
        stsAoff[i] = (uint32_t)(row * ROWSTRIDE + slot * 8);
    }
    // ---- B fill: 256 float4, one per thread ----
    int rb = tid >> 2, kq = tid & 3;
    int dffcol = bx * 32 + (rb >> 1);
    const float* bwp = ((rb & 1) ? w1 : w0) + ((size_t)e * DFF_DIM + dffcol) * D_DIM + kq * 4;
    uint32_t stsB = (uint32_t)(rb * ROWSTRIDE + kq * 8);

    // ---- ldmatrix per-lane offsets ----
    int li = lane & 7;
    uint32_t offA = (uint32_t)((wr * 32 + ((lane >> 3) & 1) * 8 + li) * ROWSTRIDE
                               + ((lane >> 4) & 1) * 16);
    uint32_t offB = (uint32_t)((wc * 32 + ((lane >> 4) & 1) * 8 + li) * ROWSTRIDE
                               + ((lane >> 3) & 1) * 16);

    float acc[2][4][4];
    #pragma unroll
    for (int i = 0; i < 2; i++)
        #pragma unroll
        for (int j = 0; j < 4; j++)
            #pragma unroll
            for (int c = 0; c < 4; c++) acc[i][j][c] = 0.f;

    float4 rA[2], rBv;
    auto ldg = [&](int k0) {
        #pragma unroll
        for (int i = 0; i < 2; i++)
            rA[i] = axp[i] ? *(const float4*)(axp[i] + k0) : make_float4(0.f, 0.f, 0.f, 0.f);
        rBv = *(const float4*)(bwp + k0);
    };
    auto sts = [&](int st) {
        char* base = smem + st * STAGE1;
        #pragma unroll
        for (int i = 0; i < 2; i++) {
            uint2 hh, ll;
            cvt4(rA[i], hh, ll);
            *(uint2*)(base + A_HI + stsAoff[i]) = hh;
            *(uint2*)(base + A_LO + stsAoff[i]) = ll;
        }
        uint2 hh, ll;
        cvt4(rBv, hh, ll);
        *(uint2*)(base + B_HI + stsB) = hh;
        *(uint2*)(base + B_LO + stsB) = ll;
    };

    ldg(0); sts(0);
    __syncthreads();

    const int NKB = D_DIM / KBLK;   // 128
    for (int kb = 0; kb < NKB; kb++) {
        if (kb + 1 < NKB) ldg((kb + 1) * KBLK);
        uint32_t st = sb + (kb & 1) * STAGE1;
        uint32_t Ah[2][4], Al[2][4], Bf[2][4];
        #pragma unroll
        for (int mi = 0; mi < 2; mi++) {
            LDSM4(Ah[mi], st + A_HI + offA + mi * 16 * ROWSTRIDE);
            LDSM4(Al[mi], st + A_LO + offA + mi * 16 * ROWSTRIDE);
        }
        #pragma unroll
        for (int nj = 0; nj < 2; nj++)
            LDSM4(Bf[nj], st + B_HI + offB + nj * 16 * ROWSTRIDE);
        // HH pass
        #pragma unroll
        for (int mi = 0; mi < 2; mi++)
            #pragma unroll
            for (int nj = 0; nj < 2; nj++) {
                MMA(acc[mi][nj*2],   Ah[mi], Bf[nj][0], Bf[nj][1]);
                MMA(acc[mi][nj*2+1], Ah[mi], Bf[nj][2], Bf[nj][3]);
            }
        // LH pass (Bh still resident)
        #pragma unroll
        for (int mi = 0; mi < 2; mi++)
            #pragma unroll
            for (int nj = 0; nj < 2; nj++) {
                MMA(acc[mi][nj*2],   Al[mi], Bf[nj][0], Bf[nj][1]);
                MMA(acc[mi][nj*2+1], Al[mi], Bf[nj][2], Bf[nj][3]);
            }
        // reload B with lo plane, HL pass
        #pragma unroll
        for (int nj = 0; nj < 2; nj++)
            LDSM4(Bf[nj], st + B_LO + offB + nj * 16 * ROWSTRIDE);
        #pragma unroll
        for (int mi = 0; mi < 2; mi++)
            #pragma unroll
            for (int nj = 0; nj < 2; nj++) {
                MMA(acc[mi][nj*2],   Ah[mi], Bf[nj][0], Bf[nj][1]);
                MMA(acc[mi][nj*2+1], Ah[mi], Bf[nj][2], Bf[nj][3]);
            }
        if (kb + 1 < NKB) sts((kb + 1) & 1);
        __syncthreads();
    }

    // ---- epilogue: SwiGLU (c0=gate, c1=up of same dffcol), store H hi/lo ----
    float s0e = s0[e], s1e = s1[e];
    #pragma unroll
    for (int mi = 0; mi < 2; mi++)
        #pragma unroll
        for (int nf = 0; nf < 4; nf++) {
            int r0  = tile * BM + wr * 32 + mi * 16 + (lane >> 2);
            int col = bx * 32 + wc * 16 + nf * 4 + (lane & 3);
            float g0 = acc[mi][nf][0] * s0e, u0 = acc[mi][nf][1] * s1e;
            float g8 = acc[mi][nf][2] * s0e, u8 = acc[mi][nf][3] * s1e;
            float h0 = (g0 / (1.f + __expf(-g0))) * u0;
            float h8 = (g8 / (1.f + __expf(-g8))) * u8;
            size_t o0 = (size_t)r0 * DFF_DIM + col;
            size_t o8 = o0 + (size_t)8 * DFF_DIM;
            __nv_bfloat16 b0 = __float2bfloat16(h0);
            __nv_bfloat16 b8 = __float2bfloat16(h8);
            g_Hhi[o0] = b0; g_Hlo[o0] = __float2bfloat16(h0 - __bfloat162float(b0));
            g_Hhi[o8] = b8; g_Hlo[o8] = __float2bfloat16(h8 - __bfloat162float(b8));
        }
}

// ---------------- GEMM2: H @ w2^T * s2 -> Y ----------------
// CTA 128 rows x 64 d-cols. Warp grid 4x2, warp tile 32x32. KBLK=16.
__global__ void __launch_bounds__(256, 3) gemm2_mma(
    const float* __restrict__ w2, const float* __restrict__ s2)
{
    int tile = blockIdx.y;
    if (tile >= g_ntiles) return;
    int e  = g_tile_e[tile];
    int bx = blockIdx.x;

    extern __shared__ char smem[];
    uint32_t sb = smem_u32(smem);
    int tid = threadIdx.x, lane = tid & 31, wid = tid >> 5;
    int wr = wid >> 1, wc = wid & 1;

    // ---- A fill (H bf16 hi/lo): one uint4 per plane per thread ----
    int arow = tid >> 1, ahalf = tid & 1;
    size_t aoff = (size_t)(tile * BM + arow) * DFF_DIM + ahalf * 8;
    const __nv_bfloat16* ahp = g_Hhi + aoff;
    const __nv_bfloat16* alp = g_Hlo + aoff;
    uint32_t stsA = (uint32_t)(arow * ROWSTRIDE + ahalf * 16);

    int rb = tid >> 2, kq = tid & 3;
    const float* bwp = w2 + ((size_t)e * D_DIM + bx * 64 + rb) * DFF_DIM + kq * 4;
    uint32_t stsB = (uint32_t)(rb * ROWSTRIDE + kq * 8);

    int li = lane & 7;
    uint32_t offA = (uint32_t)((wr * 32 + ((lane >> 3) & 1) * 8 + li) * ROWSTRIDE
                               + ((lane >> 4) & 1) * 16);
    uint32_t offB = (uint32_t)((wc * 32 + ((lane >> 4) & 1) * 8 + li) * ROWSTRIDE
                               + ((lane >> 3) & 1) * 16);

    float acc[2][4][4];
    #pragma unroll
    for (int i = 0; i < 2; i++)
        #pragma unroll
        for (int j = 0; j < 4; j++)
            #pragma unroll
            for (int c = 0; c < 4; c++) acc[i][j][c] = 0.f;

    uint4 hA, lA;
    float4 rBv;
    auto ldg = [&](int k0) {
        hA = *(const uint4*)(ahp + k0);
        lA = *(const uint4*)(alp + k0);
        rBv = *(const float4*)(bwp + k0);
    };
    auto sts = [&](int st) {
        char* base = smem + st * STAGE1;
        *(uint4*)(base + A_HI + stsA) = hA;
        *(uint4*)(base + A_LO + stsA) = lA;
        uint2 hh, ll;
        cvt4(rBv, hh, ll);
        *(uint2*)(base + B_HI + stsB) = hh;
        *(uint2*)(base + B_LO + stsB) = ll;
    };

    ldg(0); sts(0);
    __syncthreads();

    const int NKB = DFF_DIM / KBLK;   // 64
    for (int kb = 0; kb < NKB; kb++) {
        if (kb + 1 < NKB) ldg((kb + 1) * KBLK);
        uint32_t st = sb + (kb & 1) * STAGE1;
        uint32_t Ah[2][4], Al[2][4], Bf[2][4];
        #pragma unroll
        for (int mi = 0; mi < 2; mi++) {
            LDSM4(Ah[mi], st + A_HI + offA + mi * 16 * ROWSTRIDE);
            LDSM4(Al[mi], st + A_LO + offA + mi * 16 * ROWSTRIDE);
        }
        #pragma unroll
        for (int nj = 0; nj < 2; nj++)
            LDSM4(Bf[nj], st + B_HI + offB + nj * 16 * ROWSTRIDE);
        #pragma unroll
        for (int mi = 0; mi < 2; mi++)
            #pragma unroll
            for (int nj = 0; nj < 2; nj++) {
                MMA(acc[mi][nj*2],   Ah[mi], Bf[nj][0], Bf[nj][1]);
                MMA(acc[mi][nj*2+1], Ah[mi], Bf[nj][2], Bf[nj][3]);
            }
        #pragma unroll
        for (int mi = 0; mi < 2; mi++)
            #pragma unroll
            for (int nj = 0; nj < 2; nj++) {
                MMA(acc[mi][nj*2],   Al[mi], Bf[nj][0], Bf[nj][1]);
                MMA(acc[mi][nj*2+1], Al[mi], Bf[nj][2], Bf[nj][3]);
            }
        #pragma unroll
        for (int nj = 0; nj < 2; nj++)
            LDSM4(Bf[nj], st + B_LO + offB + nj * 16 * ROWSTRIDE);
        #pragma unroll
        for (int mi = 0; mi < 2; mi++)
            #pragma unroll
            for (int nj = 0; nj < 2; nj++) {
                MMA(acc[mi][nj*2],   Ah[mi], Bf[nj][0], Bf[nj][1]);
                MMA(acc[mi][nj*2+1], Ah[mi], Bf[nj][2], Bf[nj][3]);
            }
        if (kb + 1 < NKB) sts((kb + 1) & 1);
        __syncthreads();
    }

    float s2e = s2[e];
    #pragma unroll
    for (int mi = 0; mi < 2; mi++)
        #pragma unroll
        for (int nf = 0; nf < 4; nf++) {
            int r0  = tile * BM + wr * 32 + mi * 16 + (lane >> 2);
            int col = bx * 64 + wc * 32 + nf * 8 + 2 * (lane & 3);
            float2 v0 = make_float2(acc[mi][nf][0] * s2e, acc[mi][nf][1] * s2e);
            float2 v8 = make_float2(acc[mi][nf][2] * s2e, acc[mi][nf][3] * s2e);
            *(float2*)(g_Y + (size_t)r0 * D_DIM + col) = v0;
            *(float2*)(g_Y + (size_t)(r0 + 8) * D_DIM + col) = v8;
        }
}

// ---------------- final gather: out[t] = sum_k rw[t,k] * Y[slot(t,k)] ----------------
__global__ void gather_kernel(float* __restrict__ out, const float* __restrict__ rw) {
    int idx = blockIdx.x * blockDim.x + threadIdx.x;
    int t = idx >> 9;
    int q = (idx & 511) * 4;
    float4 acc = make_float4(0.f, 0.f, 0.f, 0.f);
    #pragma unroll
    for (int k = 0; k < K_TOP; k++) {
        int p = t * K_TOP + k;
        float w = rw[p];
        const float4 v = *(const float4*)(g_Y + (size_t)g_slot[p] * D_DIM + q);
        acc.x += w * v.x; acc.y += w * v.y; acc.z += w * v.z; acc.w += w * v.w;
    }
    *(float4*)(out + (size_t)t * D_DIM + q) = acc;
}

// ---------------- launch ----------------
extern "C" void kernel_launch(void* const* d_in, const int* in_sizes, int n_in,
                              void* d_out, int out_size) {
    const float* x   = (const float*)d_in[0];
    const float* w0  = (const float*)d_in[1];
    const float* w1  = (const float*)d_in[2];
    const float* w2  = (const float*)d_in[3];
    const float* s0  = (const float*)d_in[4];
    const float* s1  = (const float*)d_in[5];
    const float* s2  = (const float*)d_in[6];
    const void*  sel = d_in[7];
    const float* rw  = (const float*)d_in[8];
    float* out = (float*)d_out;

    cudaFuncSetAttribute(gemm1_mma, cudaFuncAttributeMaxDynamicSharedMemorySize, SMEM_BYTES);
    cudaFuncSetAttribute(gemm2_mma, cudaFuncAttributeMaxDynamicSharedMemorySize, SMEM_BYTES);

    prep0_kernel<<<(P_PAD + 255) / 256, 256>>>(sel);
    count_kernel<<<(P_PAIR + 255) / 256, 256>>>(sel);
    setup_fill_kernel<<<1, 256>>>(sel);
    gemm1_mma<<<dim3(DFF_DIM / 32, MAX_TILES), 256, SMEM_BYTES>>>(x, w0, w1, s0, s1);
    gemm2_mma<<<dim3(D_DIM / 64, MAX_TILES), 256, SMEM_BYTES>>>(w2, s2);
    gather_kernel<<<(T_TOK * 512) / 256, 256>>>(out, rw);
}

// round 12
// speedup vs baseline: 1.3498x; 1.3498x over previous
#include <cuda_runtime.h>
#include <cuda_fp16.h>
#include <math.h>
#include <stdint.h>

// ---------------- problem constants ----------------
#define T_TOK   1024
#define D_DIM   2048
#define DFF_DIM 1024
#define E_EXP   16
#define K_TOP   6
#define P_PAIR  (T_TOK * K_TOP)          // 6144
#define BM      128
#define P_PAD   (P_PAIR + E_EXP * BM)    // 8192
#define MAX_TILES (P_PAD / BM)           // 64
#define KBLK    32

// smem stage: A hi/lo planes (128 rows), B hi plane (64 rows), 80B row stride
#define ROWSTRIDE 80
#define A_HI 0
#define A_LO 10240
#define B_HI 20480
#define STAGE1 25600
#define SMEM_BYTES (2 * STAGE1)          // 51200, double buffered; 2 CTA/SM

// ---------------- static device scratch ----------------
__device__ int   g_rows[P_PAD];
__device__ int   g_slot[P_PAIR];
__device__ int   g_cnt [E_EXP];
__device__ int   g_cur [E_EXP];
__device__ int   g_tile_e[MAX_TILES];
__device__ int   g_ntiles;
__device__ int   g_sel64;
__device__ __half g_Hhi[(size_t)P_PAD * DFF_DIM];   // 16 MB
__device__ __half g_Hlo[(size_t)P_PAD * DFF_DIM];   // 16 MB
__device__ float  g_Y  [(size_t)P_PAD * D_DIM];     // 64 MB

// ---------------- helpers ----------------
__device__ __forceinline__ uint32_t smem_u32(const void* p) {
    uint32_t a;
    asm("{ .reg .u64 t; cvta.to.shared.u64 t, %1; cvt.u32.u64 %0, t; }" : "=r"(a) : "l"(p));
    return a;
}

#define LDSM4(r, addr)                                                        \
    asm volatile("ldmatrix.sync.aligned.m8n8.x4.shared.b16 {%0,%1,%2,%3}, [%4];" \
        : "=r"((r)[0]), "=r"((r)[1]), "=r"((r)[2]), "=r"((r)[3]) : "r"(addr))

#define MMAH(c, a, b0, b1)                                                    \
    asm volatile("mma.sync.aligned.m16n8k16.row.col.f32.f16.f16.f32 "         \
        "{%0,%1,%2,%3}, {%4,%5,%6,%7}, {%8,%9}, {%0,%1,%2,%3};"               \
        : "+f"((c)[0]), "+f"((c)[1]), "+f"((c)[2]), "+f"((c)[3])              \
        : "r"((a)[0]), "r"((a)[1]), "r"((a)[2]), "r"((a)[3]), "r"(b0), "r"(b1))

// fp32x4 -> fp16 hi (uint2) + fp16 lo (uint2); near-error-free split
__device__ __forceinline__ void cvt4_split(float4 v, uint2& hh, uint2& ll) {
    float f[4] = {v.x, v.y, v.z, v.w};
    uint32_t h[4], l[4];
    #pragma unroll
    for (int i = 0; i < 4; i++) {
        __half bh = __float2half_rn(f[i]);
        __half bl = __float2half_rn(f[i] - __half2float(bh));
        h[i] = (uint32_t)__half_as_ushort(bh);
        l[i] = (uint32_t)__half_as_ushort(bl);
    }
    hh = make_uint2(h[0] | (h[1] << 16), h[2] | (h[3] << 16));
    ll = make_uint2(l[0] | (l[1] << 16), l[2] | (l[3] << 16));
}
// fp32x8 -> fp16 (uint4), single rounding (for weights)
__device__ __forceinline__ void cvt8_round(float4 a, float4 b, uint4& hh) {
    float f[8] = {a.x, a.y, a.z, a.w, b.x, b.y, b.z, b.w};
    uint32_t h[8];
    #pragma unroll
    for (int i = 0; i < 8; i++)
        h[i] = (uint32_t)__half_as_ushort(__float2half_rn(f[i]));
    hh = make_uint4(h[0] | (h[1] << 16), h[2] | (h[3] << 16),
                    h[4] | (h[5] << 16), h[6] | (h[7] << 16));
}

// ---------------- prep0: init scratch + dtype detection ----------------
__global__ void prep0_kernel(const void* sel) {
    int i = blockIdx.x * blockDim.x + threadIdx.x;
    if (i < P_PAD) g_rows[i] = -1;
    if (i < E_EXP) { g_cnt[i] = 0; g_cur[i] = 0; }
    if (blockIdx.x == 0) {
        __shared__ int bad;
        if (threadIdx.x == 0) bad = 0;
        __syncthreads();
        const int* w = (const int*)sel;
        for (int j = threadIdx.x; j < 1024; j += blockDim.x) {
            int lo = w[2 * j], hi = w[2 * j + 1];
            if (hi != 0 || (unsigned)lo >= E_EXP) atomicOr(&bad, 1);
        }
        __syncthreads();
        if (threadIdx.x == 0) g_sel64 = bad ? 0 : 1;
    }
}
__device__ __forceinline__ int load_expert(const void* sel, int p) {
    int e = g_sel64 ? (int)((const long long*)sel)[p] : ((const int*)sel)[p];
    return e & (E_EXP - 1);
}

__global__ void count_kernel(const void* __restrict__ sel) {
    int p = blockIdx.x * blockDim.x + threadIdx.x;
    if (p < P_PAIR) atomicAdd(&g_cnt[load_expert(sel, p)], 1);
}

__global__ void setup_fill_kernel(const void* __restrict__ sel) {
    __shared__ int basepad[E_EXP];
    if (threadIdx.x == 0) {
        int pos = 0;
        for (int e = 0; e < E_EXP; e++) {
            basepad[e] = pos;
            int tiles = (g_cnt[e] + BM - 1) / BM;
            for (int i = 0; i < tiles; i++) g_tile_e[pos / BM + i] = e;
            pos += tiles * BM;
        }
        g_ntiles = pos / BM;
    }
    __syncthreads();
    for (int p = threadIdx.x; p < P_PAIR; p += blockDim.x) {
        int e = load_expert(sel, p);
        int idx = basepad[e] + atomicAdd(&g_cur[e], 1);
        g_rows[idx] = p / K_TOP;
        g_slot[p] = idx;
    }
}

// ---------------- GEMM1: x @ [w0|w1 interleaved]^T -> SwiGLU -> H ----------------
// CTA 128 rows x 64 interleaved n (= 32 dff cols). Warp grid 4x2, warp tile 32x32.
// fp16 2-pass: A split hi/lo, B rounded once. grid (bx fastest, tile slow).
__global__ void __launch_bounds__(256, 2) gemm1_mma(
    const float* __restrict__ x,  const float* __restrict__ w0,
    const float* __restrict__ w1, const float* __restrict__ s0,
    const float* __restrict__ s1)
{
    int tile = blockIdx.y;
    if (tile >= g_ntiles) return;
    int e  = g_tile_e[tile];
    int bx = blockIdx.x;

    extern __shared__ char smem[];
    uint32_t sb = smem_u32(smem);
    int tid = threadIdx.x, lane = tid & 31, wid = tid >> 5;
    int wr = wid >> 1, wc = wid & 1;

    // ---- A fill: flat float4 mapping, fully coalesced ----
    const float* axp[4];
    uint32_t stsAoff[4];
    #pragma unroll
    for (int i = 0; i < 4; i++) {
        int idx = i * 256 + tid;
        int row = idx >> 3, slot = idx & 7;        // row 0..127, slot 0..7 (float4)
        int grow = g_rows[tile * BM + row];
        axp[i] = (grow >= 0) ? x + (size_t)grow * D_DIM + slot * 4 : (const float*)0;
        stsAoff[i] = (uint32_t)(row * ROWSTRIDE + slot * 8);
    }
    // ---- B fill: 64 rows x 4 k-quarters ----
    int rb = tid >> 2, kq = tid & 3;
    int dffcol = bx * 32 + (rb >> 1);
    const float* bwp = ((rb & 1) ? w1 : w0) + ((size_t)e * DFF_DIM + dffcol) * D_DIM + kq * 8;
    uint32_t stsB = (uint32_t)(rb * ROWSTRIDE + kq * 16);

    // ---- ldmatrix per-lane offsets ----
    int li = lane & 7;
    uint32_t offA = (uint32_t)((wr * 32 + ((lane >> 3) & 1) * 8 + li) * ROWSTRIDE
                               + ((lane >> 4) & 1) * 16);
    uint32_t offB = (uint32_t)((wc * 32 + ((lane >> 4) & 1) * 8 + li) * ROWSTRIDE
                               + ((lane >> 3) & 1) * 16);

    float acc[2][4][4];
    #pragma unroll
    for (int i = 0; i < 2; i++)
        #pragma unroll
        for (int j = 0; j < 4; j++)
            #pragma unroll
            for (int c = 0; c < 4; c++) acc[i][j][c] = 0.f;

    float4 rA[4], rB[2];
    auto ldg = [&](int k0) {
        #pragma unroll
        for (int i = 0; i < 4; i++)
            rA[i] = axp[i] ? *(const float4*)(axp[i] + k0) : make_float4(0.f, 0.f, 0.f, 0.f);
        rB[0] = *(const float4*)(bwp + k0);
        rB[1] = *(const float4*)(bwp + k0 + 4);
    };
    auto sts = [&](int st) {
        char* base = smem + st * STAGE1;
        #pragma unroll
        for (int i = 0; i < 4; i++) {
            uint2 hh, ll;
            cvt4_split(rA[i], hh, ll);
            *(uint2*)(base + A_HI + stsAoff[i]) = hh;
            *(uint2*)(base + A_LO + stsAoff[i]) = ll;
        }
        uint4 bh;
        cvt8_round(rB[0], rB[1], bh);
        *(uint4*)(base + B_HI + stsB) = bh;
    };

    ldg(0); sts(0);
    __syncthreads();

    const int NKB = D_DIM / KBLK;   // 64
    for (int kb = 0; kb < NKB; kb++) {
        if (kb + 1 < NKB) ldg((kb + 1) * KBLK);
        uint32_t st = sb + (kb & 1) * STAGE1;
        #pragma unroll
        for (int s = 0; s < 2; s++) {
            uint32_t Ah[2][4], Al[2][4], Bh[2][4];
            #pragma unroll
            for (int nj = 0; nj < 2; nj++)
                LDSM4(Bh[nj], st + B_HI + offB + nj * 16 * ROWSTRIDE + s * 32);
            #pragma unroll
            for (int mi = 0; mi < 2; mi++) {
                LDSM4(Ah[mi], st + A_HI + offA + mi * 16 * ROWSTRIDE + s * 32);
                LDSM4(Al[mi], st + A_LO + offA + mi * 16 * ROWSTRIDE + s * 32);
            }
            // pass 1: Ah x Bh
            #pragma unroll
            for (int mi = 0; mi < 2; mi++)
                #pragma unroll
                for (int nj = 0; nj < 2; nj++) {
                    MMAH(acc[mi][nj*2],   Ah[mi], Bh[nj][0], Bh[nj][1]);
                    MMAH(acc[mi][nj*2+1], Ah[mi], Bh[nj][2], Bh[nj][3]);
                }
            // pass 2: Al x Bh
            #pragma unroll
            for (int mi = 0; mi < 2; mi++)
                #pragma unroll
                for (int nj = 0; nj < 2; nj++) {
                    MMAH(acc[mi][nj*2],   Al[mi], Bh[nj][0], Bh[nj][1]);
                    MMAH(acc[mi][nj*2+1], Al[mi], Bh[nj][2], Bh[nj][3]);
                }
        }
        if (kb + 1 < NKB) sts((kb + 1) & 1);
        __syncthreads();
    }

    // ---- epilogue: SwiGLU (c0=gate, c1=up of same dffcol), store H hi/lo fp16 ----
    float s0e = s0[e], s1e = s1[e];
    #pragma unroll
    for (int mi = 0; mi < 2; mi++)
        #pragma unroll
        for (int nf = 0; nf < 4; nf++) {
            int r0  = tile * BM + wr * 32 + mi * 16 + (lane >> 2);
            int col = bx * 32 + wc * 16 + nf * 4 + (lane & 3);
            float g0 = acc[mi][nf][0] * s0e, u0 = acc[mi][nf][1] * s1e;
            float g8 = acc[mi][nf][2] * s0e, u8 = acc[mi][nf][3] * s1e;
            float h0 = (g0 / (1.f + __expf(-g0))) * u0;
            float h8 = (g8 / (1.f + __expf(-g8))) * u8;
            size_t o0 = (size_t)r0 * DFF_DIM + col;
            size_t o8 = o0 + (size_t)8 * DFF_DIM;
            __half b0 = __float2half_rn(h0);
            __half b8 = __float2half_rn(h8);
            g_Hhi[o0] = b0; g_Hlo[o0] = __float2half_rn(h0 - __half2float(b0));
            g_Hhi[o8] = b8; g_Hlo[o8] = __float2half_rn(h8 - __half2float(b8));
        }
}

// ---------------- GEMM2: H @ w2^T * s2 -> Y ----------------
// CTA 128 rows x 64 d-cols. Warp grid 4x2, warp tile 32x32. fp16 2-pass.
__global__ void __launch_bounds__(256, 2) gemm2_mma(
    const float* __restrict__ w2, const float* __restrict__ s2)
{
    int tile = blockIdx.y;
    if (tile >= g_ntiles) return;
    int e  = g_tile_e[tile];
    int bx = blockIdx.x;

    extern __shared__ char smem[];
    uint32_t sb = smem_u32(smem);
    int tid = threadIdx.x, lane = tid & 31, wid = tid >> 5;
    int wr = wid >> 1, wc = wid & 1;

    // ---- A fill (H fp16 hi/lo): flat uint4 mapping ----
    const __half* ahp[2];
    const __half* alp[2];
    uint32_t stsAoff[2];
    #pragma unroll
    for (int i = 0; i < 2; i++) {
        int idx = i * 256 + tid;
        int row = idx >> 2, slot = idx & 3;        // row 0..127, slot 0..3 (uint4 = 8 fp16)
        size_t off = (size_t)(tile * BM + row) * DFF_DIM + slot * 8;
        ahp[i] = g_Hhi + off;
        alp[i] = g_Hlo + off;
        stsAoff[i] = (uint32_t)(row * ROWSTRIDE + slot * 16);
    }
    int rb = tid >> 2, kq = tid & 3;
    const float* bwp = w2 + ((size_t)e * D_DIM + bx * 64 + rb) * DFF_DIM + kq * 8;
    uint32_t stsB = (uint32_t)(rb * ROWSTRIDE + kq * 16);

    int li = lane & 7;
    uint32_t offA = (uint32_t)((wr * 32 + ((lane >> 3) & 1) * 8 + li) * ROWSTRIDE
                               + ((lane >> 4) & 1) * 16);
    uint32_t offB = (uint32_t)((wc * 32 + ((lane >> 4) & 1) * 8 + li) * ROWSTRIDE
                               + ((lane >> 3) & 1) * 16);

    float acc[2][4][4];
    #pragma unroll
    for (int i = 0; i < 2; i++)
        #pragma unroll
        for (int j = 0; j < 4; j++)
            #pragma unroll
            for (int c = 0; c < 4; c++) acc[i][j][c] = 0.f;

    uint4 hA[2], lA[2];
    float4 rB[2];
    auto ldg = [&](int k0) {
        #pragma unroll
        for (int i = 0; i < 2; i++) {
            hA[i] = *(const uint4*)(ahp[i] + k0);
            lA[i] = *(const uint4*)(alp[i] + k0);
        }
        rB[0] = *(const float4*)(bwp + k0);
        rB[1] = *(const float4*)(bwp + k0 + 4);
    };
    auto sts = [&](int st) {
        char* base = smem + st * STAGE1;
        #pragma unroll
        for (int i = 0; i < 2; i++) {
            *(uint4*)(base + A_HI + stsAoff[i]) = hA[i];
            *(uint4*)(base + A_LO + stsAoff[i]) = lA[i];
        }
        uint4 bh;
        cvt8_round(rB[0], rB[1], bh);
        *(uint4*)(base + B_HI + stsB) = bh;
    };

    ldg(0); sts(0);
    __syncthreads();

    const int NKB = DFF_DIM / KBLK;   // 32
    for (int kb = 0; kb < NKB; kb++) {
        if (kb + 1 < NKB) ldg((kb + 1) * KBLK);
        uint32_t st = sb + (kb & 1) * STAGE1;
        #pragma unroll
        for (int s = 0; s < 2; s++) {
            uint32_t Ah[2][4], Al[2][4], Bh[2][4];
            #pragma unroll
            for (int nj = 0; nj < 2; nj++)
                LDSM4(Bh[nj], st + B_HI + offB + nj * 16 * ROWSTRIDE + s * 32);
            #pragma unroll
            for (int mi = 0; mi < 2; mi++) {
                LDSM4(Ah[mi], st + A_HI + offA + mi * 16 * ROWSTRIDE + s * 32);
                LDSM4(Al[mi], st + A_LO + offA + mi * 16 * ROWSTRIDE + s * 32);
            }
            #pragma unroll
            for (int mi = 0; mi < 2; mi++)
                #pragma unroll
                for (int nj = 0; nj < 2; nj++) {
                    MMAH(acc[mi][nj*2],   Ah[mi], Bh[nj][0], Bh[nj][1]);
                    MMAH(acc[mi][nj*2+1], Ah[mi], Bh[nj][2], Bh[nj][3]);
                }
            #pragma unroll
            for (int mi = 0; mi < 2; mi++)
                #pragma unroll
                for (int nj = 0; nj < 2; nj++) {
                    MMAH(acc[mi][nj*2],   Al[mi], Bh[nj][0], Bh[nj][1]);
                    MMAH(acc[mi][nj*2+1], Al[mi], Bh[nj][2], Bh[nj][3]);
                }
        }
        if (kb + 1 < NKB) sts((kb + 1) & 1);
        __syncthreads();
    }

    float s2e = s2[e];
    #pragma unroll
    for (int mi = 0; mi < 2; mi++)
        #pragma unroll
        for (int nf = 0; nf < 4; nf++) {
            int r0  = tile * BM + wr * 32 + mi * 16 + (lane >> 2);
            int col = bx * 64 + wc * 32 + nf * 8 + 2 * (lane & 3);
            float2 v0 = make_float2(acc[mi][nf][0] * s2e, acc[mi][nf][1] * s2e);
            float2 v8 = make_float2(acc[mi][nf][2] * s2e, acc[mi][nf][3] * s2e);
            *(float2*)(g_Y + (size_t)r0 * D_DIM + col) = v0;
            *(float2*)(g_Y + (size_t)(r0 + 8) * D_DIM + col) = v8;
        }
}

// ---------------- final gather: out[t] = sum_k rw[t,k] * Y[slot(t,k)] ----------------
__global__ void gather_kernel(float* __restrict__ out, const float* __restrict__ rw) {
    int idx = blockIdx.x * blockDim.x + threadIdx.x;
    int t = idx >> 9;
    int q = (idx & 511) * 4;
    float4 acc = make_float4(0.f, 0.f, 0.f, 0.f);
    #pragma unroll
    for (int k = 0; k < K_TOP; k++) {
        int p = t * K_TOP + k;
        float w = rw[p];
        const float4 v = *(const float4*)(g_Y + (size_t)g_slot[p] * D_DIM + q);
        acc.x += w * v.x; acc.y += w * v.y; acc.z += w * v.z; acc.w += w * v.w;
    }
    *(float4*)(out + (size_t)t * D_DIM + q) = acc;
}

// ---------------- launch ----------------
extern "C" void kernel_launch(void* const* d_in, const int* in_sizes, int n_in,
                              void* d_out, int out_size) {
    const float* x   = (const float*)d_in[0];
    const float* w0  = (const float*)d_in[1];
    const float* w1  = (const float*)d_in[2];
    const float* w2  = (const float*)d_in[3];
    const float* s0  = (const float*)d_in[4];
    const float* s1  = (const float*)d_in[5];
    const float* s2  = (const float*)d_in[6];
    const void*  sel = d_in[7];
    const float* rw  = (const float*)d_in[8];
    float* out = (float*)d_out;

    cudaFuncSetAttribute(gemm1_mma, cudaFuncAttributeMaxDynamicSharedMemorySize, SMEM_BYTES);
    cudaFuncSetAttribute(gemm2_mma, cudaFuncAttributeMaxDynamicSharedMemorySize, SMEM_BYTES);

    prep0_kernel<<<(P_PAD + 255) / 256, 256>>>(sel);
    count_kernel<<<(P_PAIR + 255) / 256, 256>>>(sel);
    setup_fill_kernel<<<1, 256>>>(sel);
    gemm1_mma<<<dim3(DFF_DIM / 32, MAX_TILES), 256, SMEM_BYTES>>>(x, w0, w1, s0, s1);
    gemm2_mma<<<dim3(D_DIM / 64, MAX_TILES), 256, SMEM_BYTES>>>(w2, s2);
    gather_kernel<<<(T_TOK * 512) / 256, 256>>>(out, rw);
}

// round 13
// speedup vs baseline: 1.4699x; 1.0890x over previous
#include <cuda_runtime.h>
#include <cuda_fp16.h>
#include <math.h>
#include <stdint.h>

// ---------------- problem constants ----------------
#define T_TOK   1024
#define D_DIM   2048
#define DFF_DIM 1024
#define E_EXP   16
#define K_TOP   6
#define P_PAIR  (T_TOK * K_TOP)          // 6144
#define BM      128
#define P_PAD   (P_PAIR + E_EXP * BM)    // 8192
#define MAX_TILES (P_PAD / BM)           // 64
#define KBLK    32
#define WN4     ((E_EXP * DFF_DIM * D_DIM) / 4)   // 8388608 float4 per weight tensor

// smem stage: A hi/lo planes (128 rows), B plane (64 rows), 80B row stride
#define ROWSTRIDE 80
#define A_HI 0
#define A_LO 10240
#define B_HI 20480
#define STAGE1 25600
#define NSTAGE 3
#define SMEM_BYTES (NSTAGE * STAGE1)     // 76800; 2 CTA/SM -> 153.6KB

// ---------------- static device scratch ----------------
__device__ int   g_rows[P_PAD];
__device__ int   g_slot[P_PAIR];
__device__ int   g_cnt [E_EXP];
__device__ int   g_cur [E_EXP];
__device__ int   g_tile_e[MAX_TILES];
__device__ int   g_ntiles;
__device__ int   g_sel64;
__device__ __half g_xhi[(size_t)T_TOK * D_DIM];       // 4 MB
__device__ __half g_xlo[(size_t)T_TOK * D_DIM];       // 4 MB
__device__ __half g_w0h[(size_t)E_EXP * DFF_DIM * D_DIM];  // 64 MB
__device__ __half g_w1h[(size_t)E_EXP * DFF_DIM * D_DIM];  // 64 MB
__device__ __half g_w2h[(size_t)E_EXP * D_DIM * DFF_DIM];  // 64 MB
__device__ __half g_Hhi[(size_t)P_PAD * DFF_DIM];     // 16 MB
__device__ __half g_Hlo[(size_t)P_PAD * DFF_DIM];     // 16 MB
__device__ float  g_Y  [(size_t)P_PAD * D_DIM];       // 64 MB

// ---------------- helpers ----------------
__device__ __forceinline__ uint32_t smem_u32(const void* p) {
    uint32_t a;
    asm("{ .reg .u64 t; cvta.to.shared.u64 t, %1; cvt.u32.u64 %0, t; }" : "=r"(a) : "l"(p));
    return a;
}

#define LDSM4(r, addr)                                                        \
    asm volatile("ldmatrix.sync.aligned.m8n8.x4.shared.b16 {%0,%1,%2,%3}, [%4];" \
        : "=r"((r)[0]), "=r"((r)[1]), "=r"((r)[2]), "=r"((r)[3]) : "r"(addr))

#define MMAH(c, a, b0, b1)                                                    \
    asm volatile("mma.sync.aligned.m16n8k16.row.col.f32.f16.f16.f32 "         \
        "{%0,%1,%2,%3}, {%4,%5,%6,%7}, {%8,%9}, {%0,%1,%2,%3};"               \
        : "+f"((c)[0]), "+f"((c)[1]), "+f"((c)[2]), "+f"((c)[3])              \
        : "r"((a)[0]), "r"((a)[1]), "r"((a)[2]), "r"((a)[3]), "r"(b0), "r"(b1))

#define CP_ASYNC16(dst, src)                                                  \
    asm volatile("cp.async.cg.shared.global [%0], [%1], 16;"                  \
        :: "r"(dst), "l"(src) : "memory")
#define CP_ASYNC16Z(dst, src, sz)                                             \
    asm volatile("cp.async.cg.shared.global [%0], [%1], 16, %2;"              \
        :: "r"(dst), "l"(src), "r"(sz) : "memory")
#define CP_COMMIT()  asm volatile("cp.async.commit_group;" ::: "memory")
#define CP_WAIT1()   asm volatile("cp.async.wait_group 1;" ::: "memory")

__device__ __forceinline__ uint32_t pack2h(float a, float b) {
    __half2 h = __floats2half2_rn(a, b);
    return *(uint32_t*)&h;
}

// ---------------- weight conversion: fp32 -> fp16 ----------------
__global__ void convh_kernel(const float* __restrict__ s, int which, int n4) {
    int i = blockIdx.x * blockDim.x + threadIdx.x;
    if (i >= n4) return;
    __half* d = (which == 0) ? g_w0h : (which == 1) ? g_w1h : g_w2h;
    float4 v = ((const float4*)s)[i];
    ((uint2*)d)[i] = make_uint2(pack2h(v.x, v.y), pack2h(v.z, v.w));
}

// ---------------- x split: fp32 -> fp16 hi + lo (exact) ----------------
__global__ void splitx_kernel(const float* __restrict__ x) {
    int i = blockIdx.x * blockDim.x + threadIdx.x;
    if (i >= (T_TOK * D_DIM) / 4) return;
    float4 v = ((const float4*)x)[i];
    float f[4] = {v.x, v.y, v.z, v.w};
    uint32_t h[4], l[4];
    #pragma unroll
    for (int j = 0; j < 4; j++) {
        __half bh = __float2half_rn(f[j]);
        __half bl = __float2half_rn(f[j] - __half2float(bh));
        h[j] = (uint32_t)__half_as_ushort(bh);
        l[j] = (uint32_t)__half_as_ushort(bl);
    }
    ((uint2*)g_xhi)[i] = make_uint2(h[0] | (h[1] << 16), h[2] | (h[3] << 16));
    ((uint2*)g_xlo)[i] = make_uint2(l[0] | (l[1] << 16), l[2] | (l[3] << 16));
}

// ---------------- prep0: init scratch + dtype detection ----------------
__global__ void prep0_kernel(const void* sel) {
    int i = blockIdx.x * blockDim.x + threadIdx.x;
    if (i < P_PAD) g_rows[i] = -1;
    if (i < E_EXP) { g_cnt[i] = 0; g_cur[i] = 0; }
    if (blockIdx.x == 0) {
        __shared__ int bad;
        if (threadIdx.x == 0) bad = 0;
        __syncthreads();
        const int* w = (const int*)sel;
        for (int j = threadIdx.x; j < 1024; j += blockDim.x) {
            int lo = w[2 * j], hi = w[2 * j + 1];
            if (hi != 0 || (unsigned)lo >= E_EXP) atomicOr(&bad, 1);
        }
        __syncthreads();
        if (threadIdx.x == 0) g_sel64 = bad ? 0 : 1;
    }
}
__device__ __forceinline__ int load_expert(const void* sel, int p) {
    int e = g_sel64 ? (int)((const long long*)sel)[p] : ((const int*)sel)[p];
    return e & (E_EXP - 1);
}

__global__ void count_kernel(const void* __restrict__ sel) {
    int p = blockIdx.x * blockDim.x + threadIdx.x;
    if (p < P_PAIR) atomicAdd(&g_cnt[load_expert(sel, p)], 1);
}

__global__ void setup_fill_kernel(const void* __restrict__ sel) {
    __shared__ int basepad[E_EXP];
    if (threadIdx.x == 0) {
        int pos = 0;
        for (int e = 0; e < E_EXP; e++) {
            basepad[e] = pos;
            int tiles = (g_cnt[e] + BM - 1) / BM;
            for (int i = 0; i < tiles; i++) g_tile_e[pos / BM + i] = e;
            pos += tiles * BM;
        }
        g_ntiles = pos / BM;
    }
    __syncthreads();
    for (int p = threadIdx.x; p < P_PAIR; p += blockDim.x) {
        int e = load_expert(sel, p);
        int idx = basepad[e] + atomicAdd(&g_cur[e], 1);
        g_rows[idx] = p / K_TOP;
        g_slot[p] = idx;
    }
}

// ---------------- GEMM1: x @ [w0|w1 interleaved]^T -> SwiGLU -> H ----------------
// CTA 128 rows x 64 interleaved n (= 32 dff cols). Warp grid 4x2, warp tile 32x32.
// fp16 2-pass (A exact hi/lo split, B rounded once). cp.async 3-stage pipeline.
__global__ void __launch_bounds__(256, 2) gemm1_mma(
    const float* __restrict__ s0, const float* __restrict__ s1)
{
    int tile = blockIdx.y;
    if (tile >= g_ntiles) return;
    int e  = g_tile_e[tile];
    int bx = blockIdx.x;

    extern __shared__ char smem[];
    uint32_t sb = smem_u32(smem);
    int tid = threadIdx.x, lane = tid & 31, wid = tid >> 5;
    int wr = wid >> 1, wc = wid & 1;

    // ---- cp.async A chunks: 1024 16B chunks (2 planes x 128 rows x 4) ----
    const char* asrc[4]; uint32_t adst[4]; uint32_t asz[4];
    #pragma unroll
    for (int i = 0; i < 4; i++) {
        int idx = i * 256 + tid;
        int pl = idx >> 9, rem = idx & 511;
        int r = rem >> 2, c = rem & 3;
        int grow = g_rows[tile * BM + r];
        const __half* base = pl ? g_xlo : g_xhi;
        asrc[i] = (const char*)(base + (size_t)(grow < 0 ? 0 : grow) * D_DIM + c * 8);
        asz[i]  = (grow < 0) ? 0u : 16u;
        adst[i] = (uint32_t)((pl ? A_LO : A_HI) + r * ROWSTRIDE + c * 16);
    }
    // ---- cp.async B chunks: 256 (64 interleaved rows x 4) ----
    int rb = tid >> 2, cq = tid & 3;
    int dffcol = bx * 32 + (rb >> 1);
    const char* bsrc = (const char*)(((rb & 1) ? g_w1h : g_w0h)
                     + (size_t)(e * DFF_DIM + dffcol) * D_DIM + cq * 8);
    uint32_t bdst = (uint32_t)(B_HI + rb * ROWSTRIDE + cq * 16);

    auto fill = [&](int stg, int kb) {
        uint32_t base = sb + stg * STAGE1;
        int koff = kb * 64;   // bytes: KBLK(32) halves
        #pragma unroll
        for (int i = 0; i < 4; i++)
            CP_ASYNC16Z(base + adst[i], asrc[i] + koff, asz[i]);
        CP_ASYNC16(base + bdst, bsrc + koff);
    };

    // ---- ldmatrix per-lane offsets ----
    int li = lane & 7;
    uint32_t offA = (uint32_t)((wr * 32 + ((lane >> 3) & 1) * 8 + li) * ROWSTRIDE
                               + ((lane >> 4) & 1) * 16);
    uint32_t offB = (uint32_t)((wc * 32 + ((lane >> 4) & 1) * 8 + li) * ROWSTRIDE
                               + ((lane >> 3) & 1) * 16);

    float acc[2][4][4];
    #pragma unroll
    for (int i = 0; i < 2; i++)
        #pragma unroll
        for (int j = 0; j < 4; j++)
            #pragma unroll
            for (int c = 0; c < 4; c++) acc[i][j][c] = 0.f;

    fill(0, 0); CP_COMMIT();
    fill(1, 1); CP_COMMIT();

    const int NKB = D_DIM / KBLK;   // 64
    int cs = 0, fs = 2;
    for (int kb = 0; kb < NKB; kb++) {
        CP_WAIT1();
        __syncthreads();
        uint32_t st = sb + cs * STAGE1;
        #pragma unroll
        for (int s = 0; s < 2; s++) {
            uint32_t Ah[2][4], Al[2][4], Bh[2][4];
            #pragma unroll
            for (int nj = 0; nj < 2; nj++)
                LDSM4(Bh[nj], st + B_HI + offB + nj * 16 * ROWSTRIDE + s * 32);
            #pragma unroll
            for (int mi = 0; mi < 2; mi++) {
                LDSM4(Ah[mi], st + A_HI + offA + mi * 16 * ROWSTRIDE + s * 32);
                LDSM4(Al[mi], st + A_LO + offA + mi * 16 * ROWSTRIDE + s * 32);
            }
            #pragma unroll
            for (int mi = 0; mi < 2; mi++)
                #pragma unroll
                for (int nj = 0; nj < 2; nj++) {
                    MMAH(acc[mi][nj*2],   Ah[mi], Bh[nj][0], Bh[nj][1]);
                    MMAH(acc[mi][nj*2+1], Ah[mi], Bh[nj][2], Bh[nj][3]);
                }
            #pragma unroll
            for (int mi = 0; mi < 2; mi++)
                #pragma unroll
                for (int nj = 0; nj < 2; nj++) {
                    MMAH(acc[mi][nj*2],   Al[mi], Bh[nj][0], Bh[nj][1]);
                    MMAH(acc[mi][nj*2+1], Al[mi], Bh[nj][2], Bh[nj][3]);
                }
        }
        if (kb + 2 < NKB) fill(fs, kb + 2);
        CP_COMMIT();                      // always commit (possibly empty group)
        cs = (cs == 2) ? 0 : cs + 1;
        fs = (fs == 2) ? 0 : fs + 1;
    }

    // ---- epilogue: SwiGLU (c0=gate, c1=up of same dffcol), store H hi/lo fp16 ----
    float s0e = s0[e], s1e = s1[e];
    #pragma unroll
    for (int mi = 0; mi < 2; mi++)
        #pragma unroll
        for (int nf = 0; nf < 4; nf++) {
            int r0  = tile * BM + wr * 32 + mi * 16 + (lane >> 2);
            int col = bx * 32 + wc * 16 + nf * 4 + (lane & 3);
            float g0 = acc[mi][nf][0] * s0e, u0 = acc[mi][nf][1] * s1e;
            float g8 = acc[mi][nf][2] * s0e, u8 = acc[mi][nf][3] * s1e;
            float h0 = (g0 / (1.f + __expf(-g0))) * u0;
            float h8 = (g8 / (1.f + __expf(-g8))) * u8;
            size_t o0 = (size_t)r0 * DFF_DIM + col;
            size_t o8 = o0 + (size_t)8 * DFF_DIM;
            __half b0 = __float2half_rn(h0);
            __half b8 = __float2half_rn(h8);
            g_Hhi[o0] = b0; g_Hlo[o0] = __float2half_rn(h0 - __half2float(b0));
            g_Hhi[o8] = b8; g_Hlo[o8] = __float2half_rn(h8 - __half2float(b8));
        }
}

// ---------------- GEMM2: H @ w2^T * s2 -> Y ----------------
// CTA 128 rows x 64 d-cols. Warp grid 4x2, warp tile 32x32. cp.async 3-stage.
__global__ void __launch_bounds__(256, 2) gemm2_mma(const float* __restrict__ s2)
{
    int tile = blockIdx.y;
    if (tile >= g_ntiles) return;
    int e  = g_tile_e[tile];
    int bx = blockIdx.x;

    extern __shared__ char smem[];
    uint32_t sb = smem_u32(smem);
    int tid = threadIdx.x, lane = tid & 31, wid = tid >> 5;
    int wr = wid >> 1, wc = wid & 1;

    // ---- cp.async A chunks (H fp16 hi/lo) ----
    const char* asrc[4]; uint32_t adst[4];
    #pragma unroll
    for (int i = 0; i < 4; i++) {
        int idx = i * 256 + tid;
        int pl = idx >> 9, rem = idx & 511;
        int r = rem >> 2, c = rem & 3;
        const __half* base = pl ? g_Hlo : g_Hhi;
        asrc[i] = (const char*)(base + (size_t)(tile * BM + r) * DFF_DIM + c * 8);
        adst[i] = (uint32_t)((pl ? A_LO : A_HI) + r * ROWSTRIDE + c * 16);
    }
    int rb = tid >> 2, cq = tid & 3;
    const char* bsrc = (const char*)(g_w2h
                     + (size_t)(e * D_DIM + bx * 64 + rb) * DFF_DIM + cq * 8);
    uint32_t bdst = (uint32_t)(B_HI + rb * ROWSTRIDE + cq * 16);

    auto fill = [&](int stg, int kb) {
        uint32_t base = sb + stg * STAGE1;
        int koff = kb * 64;
        #pragma unroll
        for (int i = 0; i < 4; i++)
            CP_ASYNC16(base + adst[i], asrc[i] + koff);
        CP_ASYNC16(base + bdst, bsrc + koff);
    };

    int li = lane & 7;
    uint32_t offA = (uint32_t)((wr * 32 + ((lane >> 3) & 1) * 8 + li) * ROWSTRIDE
                               + ((lane >> 4) & 1) * 16);
    uint32_t offB = (uint32_t)((wc * 32 + ((lane >> 4) & 1) * 8 + li) * ROWSTRIDE
                               + ((lane >> 3) & 1) * 16);

    float acc[2][4][4];
    #pragma unroll
    for (int i = 0; i < 2; i++)
        #pragma unroll
        for (int j = 0; j < 4; j++)
            #pragma unroll
            for (int c = 0; c < 4; c++) acc[i][j][c] = 0.f;

    fill(0, 0); CP_COMMIT();
    fill(1, 1); CP_COMMIT();

    const int NKB = DFF_DIM / KBLK;   // 32
    int cs = 0, fs = 2;
    for (int kb = 0; kb < NKB; kb++) {
        CP_WAIT1();
        __syncthreads();
        uint32_t st = sb + cs * STAGE1;
        #pragma unroll
        for (int s = 0; s < 2; s++) {
            uint32_t Ah[2][4], Al[2][4], Bh[2][4];
            #pragma unroll
            for (int nj = 0; nj < 2; nj++)
                LDSM4(Bh[nj], st + B_HI + offB + nj * 16 * ROWSTRIDE + s * 32);
            #pragma unroll
            for (int mi = 0; mi < 2; mi++) {
                LDSM4(Ah[mi], st + A_HI + offA + mi * 16 * ROWSTRIDE + s * 32);
                LDSM4(Al[mi], st + A_LO + offA + mi * 16 * ROWSTRIDE + s * 32);
            }
            #pragma unroll
            for (int mi = 0; mi < 2; mi++)
                #pragma unroll
                for (int nj = 0; nj < 2; nj++) {
                    MMAH(acc[mi][nj*2],   Ah[mi], Bh[nj][0], Bh[nj][1]);
                    MMAH(acc[mi][nj*2+1], Ah[mi], Bh[nj][2], Bh[nj][3]);
                }
            #pragma unroll
            for (int mi = 0; mi < 2; mi++)
                #pragma unroll
                for (int nj = 0; nj < 2; nj++) {
                    MMAH(acc[mi][nj*2],   Al[mi], Bh[nj][0], Bh[nj][1]);
                    MMAH(acc[mi][nj*2+1], Al[mi], Bh[nj][2], Bh[nj][3]);
                }
        }
        if (kb + 2 < NKB) fill(fs, kb + 2);
        CP_COMMIT();
        cs = (cs == 2) ? 0 : cs + 1;
        fs = (fs == 2) ? 0 : fs + 1;
    }

    float s2e = s2[e];
    #pragma unroll
    for (int mi = 0; mi < 2; mi++)
        #pragma unroll
        for (int nf = 0; nf < 4; nf++) {
            int r0  = tile * BM + wr * 32 + mi * 16 + (lane >> 2);
            int col = bx * 64 + wc * 32 + nf * 8 + 2 * (lane & 3);
            float2 v0 = make_float2(acc[mi][nf][0] * s2e, acc[mi][nf][1] * s2e);
            float2 v8 = make_float2(acc[mi][nf][2] * s2e, acc[mi][nf][3] * s2e);
            *(float2*)(g_Y + (size_t)r0 * D_DIM + col) = v0;
            *(float2*)(g_Y + (size_t)(r0 + 8) * D_DIM + col) = v8;
        }
}

// ---------------- final gather: out[t] = sum_k rw[t,k] * Y[slot(t,k)] ----------------
__global__ void gather_kernel(float* __restrict__ out, const float* __restrict__ rw) {
    int idx = blockIdx.x * blockDim.x + threadIdx.x;
    int t = idx >> 9;
    int q = (idx & 511) * 4;
    float4 acc = make_float4(0.f, 0.f, 0.f, 0.f);
    #pragma unroll
    for (int k = 0; k < K_TOP; k++) {
        int p = t * K_TOP + k;
        float w = rw[p];
        const float4 v = *(const float4*)(g_Y + (size_t)g_slot[p] * D_DIM + q);
        acc.x += w * v.x; acc.y += w * v.y; acc.z += w * v.z; acc.w += w * v.w;
    }
    *(float4*)(out + (size_t)t * D_DIM + q) = acc;
}

// ---------------- launch ----------------
extern "C" void kernel_launch(void* const* d_in, const int* in_sizes, int n_in,
                              void* d_out, int out_size) {
    const float* x   = (const float*)d_in[0];
    const float* w0  = (const float*)d_in[1];
    const float* w1  = (const float*)d_in[2];
    const float* w2  = (const float*)d_in[3];
    const float* s0  = (const float*)d_in[4];
    const float* s1  = (const float*)d_in[5];
    const float* s2  = (const float*)d_in[6];
    const void*  sel = d_in[7];
    const float* rw  = (const float*)d_in[8];
    float* out = (float*)d_out;

    cudaFuncSetAttribute(gemm1_mma, cudaFuncAttributeMaxDynamicSharedMemorySize, SMEM_BYTES);
    cudaFuncSetAttribute(gemm2_mma, cudaFuncAttributeMaxDynamicSharedMemorySize, SMEM_BYTES);

    // weight/activation pre-conversion to fp16 (DRAM streaming, ~90us)
    convh_kernel<<<(WN4 + 255) / 256, 256>>>(w0, 0, WN4);
    convh_kernel<<<(WN4 + 255) / 256, 256>>>(w1, 1, WN4);
    convh_kernel<<<(WN4 + 255) / 256, 256>>>(w2, 2, WN4);
    splitx_kernel<<<((T_TOK * D_DIM / 4) + 255) / 256, 256>>>(x);

    prep0_kernel<<<(P_PAD + 255) / 256, 256>>>(sel);
    count_kernel<<<(P_PAIR + 255) / 256, 256>>>(sel);
    setup_fill_kernel<<<1, 256>>>(sel);
    gemm1_mma<<<dim3(DFF_DIM / 32, MAX_TILES), 256, SMEM_BYTES>>>(s0, s1);
    gemm2_mma<<<dim3(D_DIM / 64, MAX_TILES), 256, SMEM_BYTES>>>(s2);
    gather_kernel<<<(T_TOK * 512) / 256, 256>>>(out, rw);
}

// round 14
// speedup vs baseline: 1.8071x; 1.2294x over previous
#include <cuda_runtime.h>
#include <cuda_fp16.h>
#include <math.h>
#include <stdint.h>

// ---------------- problem constants ----------------
#define T_TOK   1024
#define D_DIM   2048
#define DFF_DIM 1024
#define E_EXP   16
#define K_TOP   6
#define P_PAIR  (T_TOK * K_TOP)          // 6144
#define BM      128
#define P_PAD   (P_PAIR + E_EXP * BM)    // 8192
#define MAX_TILES (P_PAD / BM)           // 64
#define KBLK    32
#define WN4     ((E_EXP * DFF_DIM * D_DIM) / 4)   // float4 per weight tensor

// smem stage: A hi/lo planes (128 rows), B plane (128 rows), 80B row stride
#define ROWSTRIDE 80
#define A_HI 0
#define A_LO 10240
#define B_HI 20480
#define STAGE1 30720
#define NSTAGE 3
#define SMEM_BYTES (NSTAGE * STAGE1)     // 92160; 2 CTA/SM -> 184.3KB

// ---------------- static device scratch ----------------
__device__ int   g_rows[P_PAD];
__device__ int   g_slot[P_PAIR];
__device__ int   g_cnt [E_EXP];
__device__ int   g_cur [E_EXP];
__device__ int   g_tile_e[MAX_TILES];
__device__ int   g_ntiles;
__device__ int   g_sel64;
__device__ __half g_xhi[(size_t)T_TOK * D_DIM];       // 4 MB
__device__ __half g_xlo[(size_t)T_TOK * D_DIM];       // 4 MB
__device__ __half g_w0h[(size_t)E_EXP * DFF_DIM * D_DIM];  // 64 MB
__device__ __half g_w1h[(size_t)E_EXP * DFF_DIM * D_DIM];  // 64 MB
__device__ __half g_w2h[(size_t)E_EXP * D_DIM * DFF_DIM];  // 64 MB
__device__ __half g_Hhi[(size_t)P_PAD * DFF_DIM];     // 16 MB
__device__ __half g_Hlo[(size_t)P_PAD * DFF_DIM];     // 16 MB
__device__ float  g_Y  [(size_t)P_PAD * D_DIM];       // 64 MB

// ---------------- helpers ----------------
__device__ __forceinline__ uint32_t smem_u32(const void* p) {
    uint32_t a;
    asm("{ .reg .u64 t; cvta.to.shared.u64 t, %1; cvt.u32.u64 %0, t; }" : "=r"(a) : "l"(p));
    return a;
}

#define LDSM4(r, addr)                                                        \
    asm volatile("ldmatrix.sync.aligned.m8n8.x4.shared.b16 {%0,%1,%2,%3}, [%4];" \
        : "=r"((r)[0]), "=r"((r)[1]), "=r"((r)[2]), "=r"((r)[3]) : "r"(addr))

#define MMAH(c, a, b0, b1)                                                    \
    asm volatile("mma.sync.aligned.m16n8k16.row.col.f32.f16.f16.f32 "         \
        "{%0,%1,%2,%3}, {%4,%5,%6,%7}, {%8,%9}, {%0,%1,%2,%3};"               \
        : "+f"((c)[0]), "+f"((c)[1]), "+f"((c)[2]), "+f"((c)[3])              \
        : "r"((a)[0]), "r"((a)[1]), "r"((a)[2]), "r"((a)[3]), "r"(b0), "r"(b1))

#define CP_ASYNC16(dst, src)                                                  \
    asm volatile("cp.async.cg.shared.global [%0], [%1], 16;"                  \
        :: "r"(dst), "l"(src) : "memory")
#define CP_ASYNC16Z(dst, src, sz)                                             \
    asm volatile("cp.async.cg.shared.global [%0], [%1], 16, %2;"              \
        :: "r"(dst), "l"(src), "r"(sz) : "memory")
#define CP_COMMIT()  asm volatile("cp.async.commit_group;" ::: "memory")
#define CP_WAIT1()   asm volatile("cp.async.wait_group 1;" ::: "memory")

__device__ __forceinline__ uint32_t pack2h(float a, float b) {
    __half2 h = __floats2half2_rn(a, b);
    return *(uint32_t*)&h;
}

// ---------------- weight conversion: fp32 -> fp16 (all three tensors) ----------------
__global__ void convh_kernel(const float* __restrict__ w0,
                             const float* __restrict__ w1,
                             const float* __restrict__ w2) {
    int i = blockIdx.x * blockDim.x + threadIdx.x;
    if (i >= 3 * WN4) return;
    int which = i / WN4, j = i % WN4;
    const float* s = (which == 0) ? w0 : (which == 1) ? w1 : w2;
    __half* d = (which == 0) ? g_w0h : (which == 1) ? g_w1h : g_w2h;
    float4 v = ((const float4*)s)[j];
    ((uint2*)d)[j] = make_uint2(pack2h(v.x, v.y), pack2h(v.z, v.w));
}

// ---------------- x split: fp32 -> fp16 hi + lo (exact) ----------------
__global__ void splitx_kernel(const float* __restrict__ x) {
    int i = blockIdx.x * blockDim.x + threadIdx.x;
    if (i >= (T_TOK * D_DIM) / 4) return;
    float4 v = ((const float4*)x)[i];
    float f[4] = {v.x, v.y, v.z, v.w};
    uint32_t h[4], l[4];
    #pragma unroll
    for (int j = 0; j < 4; j++) {
        __half bh = __float2half_rn(f[j]);
        __half bl = __float2half_rn(f[j] - __half2float(bh));
        h[j] = (uint32_t)__half_as_ushort(bh);
        l[j] = (uint32_t)__half_as_ushort(bl);
    }
    ((uint2*)g_xhi)[i] = make_uint2(h[0] | (h[1] << 16), h[2] | (h[3] << 16));
    ((uint2*)g_xlo)[i] = make_uint2(l[0] | (l[1] << 16), l[2] | (l[3] << 16));
}

// ---------------- prep0: init scratch + dtype detection ----------------
__global__ void prep0_kernel(const void* sel) {
    int i = blockIdx.x * blockDim.x + threadIdx.x;
    if (i < P_PAD) g_rows[i] = -1;
    if (i < E_EXP) { g_cnt[i] = 0; g_cur[i] = 0; }
    if (blockIdx.x == 0) {
        __shared__ int bad;
        if (threadIdx.x == 0) bad = 0;
        __syncthreads();
        const int* w = (const int*)sel;
        for (int j = threadIdx.x; j < 1024; j += blockDim.x) {
            int lo = w[2 * j], hi = w[2 * j + 1];
            if (hi != 0 || (unsigned)lo >= E_EXP) atomicOr(&bad, 1);
        }
        __syncthreads();
        if (threadIdx.x == 0) g_sel64 = bad ? 0 : 1;
    }
}
__device__ __forceinline__ int load_expert(const void* sel, int p) {
    int e = g_sel64 ? (int)((const long long*)sel)[p] : ((const int*)sel)[p];
    return e & (E_EXP - 1);
}

__global__ void count_kernel(const void* __restrict__ sel) {
    int p = blockIdx.x * blockDim.x + threadIdx.x;
    if (p < P_PAIR) atomicAdd(&g_cnt[load_expert(sel, p)], 1);
}

__global__ void setup_fill_kernel(const void* __restrict__ sel) {
    __shared__ int basepad[E_EXP];
    if (threadIdx.x == 0) {
        int pos = 0;
        for (int e = 0; e < E_EXP; e++) {
            basepad[e] = pos;
            int tiles = (g_cnt[e] + BM - 1) / BM;
            for (int i = 0; i < tiles; i++) g_tile_e[pos / BM + i] = e;
            pos += tiles * BM;
        }
        g_ntiles = pos / BM;
    }
    __syncthreads();
    for (int p = threadIdx.x; p < P_PAIR; p += blockDim.x) {
        int e = load_expert(sel, p);
        int idx = basepad[e] + atomicAdd(&g_cur[e], 1);
        g_rows[idx] = p / K_TOP;
        g_slot[p] = idx;
    }
}

// ---------------- GEMM1: x @ [w0|w1 interleaved]^T -> SwiGLU -> H ----------------
// CTA 128 rows x 128 interleaved n (= 64 dff cols). Warp grid 4x2, warp tile 32x64.
// fp16 2-pass. cp.async 3-stage pipeline.
__global__ void __launch_bounds__(256, 2) gemm1_mma(
    const float* __restrict__ s0, const float* __restrict__ s1)
{
    int tile = blockIdx.y;
    if (tile >= g_ntiles) return;
    int e  = g_tile_e[tile];
    int bx = blockIdx.x;

    extern __shared__ char smem[];
    uint32_t sb = smem_u32(smem);
    int tid = threadIdx.x, lane = tid & 31, wid = tid >> 5;
    int wr = wid >> 1, wc = wid & 1;

    // ---- cp.async A chunks: 1024 (2 planes x 128 rows x 4) ----
    const char* asrc[4]; uint32_t adst[4]; uint32_t asz[4];
    #pragma unroll
    for (int i = 0; i < 4; i++) {
        int idx = i * 256 + tid;
        int pl = idx >> 9, rem = idx & 511;
        int r = rem >> 2, c = rem & 3;
        int grow = g_rows[tile * BM + r];
        const __half* base = pl ? g_xlo : g_xhi;
        asrc[i] = (const char*)(base + (size_t)(grow < 0 ? 0 : grow) * D_DIM + c * 8);
        asz[i]  = (grow < 0) ? 0u : 16u;
        adst[i] = (uint32_t)((pl ? A_LO : A_HI) + r * ROWSTRIDE + c * 16);
    }
    // ---- cp.async B chunks: 512 (128 interleaved rows x 4) ----
    const char* bsrc[2]; uint32_t bdst[2];
    #pragma unroll
    for (int i = 0; i < 2; i++) {
        int idx = i * 256 + tid;
        int r = idx >> 2, c = idx & 3;
        int dffcol = bx * 64 + (r >> 1);
        bsrc[i] = (const char*)(((r & 1) ? g_w1h : g_w0h)
                + (size_t)(e * DFF_DIM + dffcol) * D_DIM + c * 8);
        bdst[i] = (uint32_t)(B_HI + r * ROWSTRIDE + c * 16);
    }

    auto fill = [&](int stg, int kb) {
        uint32_t base = sb + stg * STAGE1;
        int koff = kb * 64;
        #pragma unroll
        for (int i = 0; i < 4; i++)
            CP_ASYNC16Z(base + adst[i], asrc[i] + koff, asz[i]);
        #pragma unroll
        for (int i = 0; i < 2; i++)
            CP_ASYNC16(base + bdst[i], bsrc[i] + koff);
    };

    // ---- ldmatrix per-lane offsets ----
    int li = lane & 7;
    uint32_t offA = (uint32_t)((wr * 32 + ((lane >> 3) & 1) * 8 + li) * ROWSTRIDE
                               + ((lane >> 4) & 1) * 16);
    uint32_t offB = (uint32_t)((wc * 64 + ((lane >> 4) & 1) * 8 + li) * ROWSTRIDE
                               + ((lane >> 3) & 1) * 16);

    float acc[2][8][4];
    #pragma unroll
    for (int i = 0; i < 2; i++)
        #pragma unroll
        for (int j = 0; j < 8; j++)
            #pragma unroll
            for (int c = 0; c < 4; c++) acc[i][j][c] = 0.f;

    fill(0, 0); CP_COMMIT();
    fill(1, 1); CP_COMMIT();

    const int NKB = D_DIM / KBLK;   // 64
    int cs = 0, fs = 2;
    for (int kb = 0; kb < NKB; kb++) {
        CP_WAIT1();
        __syncthreads();
        uint32_t st = sb + cs * STAGE1;
        #pragma unroll
        for (int s = 0; s < 2; s++) {
            uint32_t Ah[2][4], Al[2][4];
            #pragma unroll
            for (int mi = 0; mi < 2; mi++) {
                LDSM4(Ah[mi], st + A_HI + offA + mi * 16 * ROWSTRIDE + s * 32);
                LDSM4(Al[mi], st + A_LO + offA + mi * 16 * ROWSTRIDE + s * 32);
            }
            #pragma unroll
            for (int njp = 0; njp < 2; njp++) {      // nj pair: 2 B frags live
                uint32_t Bh[2][4];
                #pragma unroll
                for (int j = 0; j < 2; j++)
                    LDSM4(Bh[j], st + B_HI + offB + (njp * 2 + j) * 16 * ROWSTRIDE + s * 32);
                #pragma unroll
                for (int mi = 0; mi < 2; mi++)
                    #pragma unroll
                    for (int j = 0; j < 2; j++) {
                        MMAH(acc[mi][njp*4 + j*2],     Ah[mi], Bh[j][0], Bh[j][1]);
                        MMAH(acc[mi][njp*4 + j*2 + 1], Ah[mi], Bh[j][2], Bh[j][3]);
                    }
                #pragma unroll
                for (int mi = 0; mi < 2; mi++)
                    #pragma unroll
                    for (int j = 0; j < 2; j++) {
                        MMAH(acc[mi][njp*4 + j*2],     Al[mi], Bh[j][0], Bh[j][1]);
                        MMAH(acc[mi][njp*4 + j*2 + 1], Al[mi], Bh[j][2], Bh[j][3]);
                    }
            }
        }
        if (kb + 2 < NKB) fill(fs, kb + 2);
        CP_COMMIT();
        cs = (cs == 2) ? 0 : cs + 1;
        fs = (fs == 2) ? 0 : fs + 1;
    }

    // ---- epilogue: SwiGLU (c0=gate, c1=up of same dffcol), store H hi/lo fp16 ----
    float s0e = s0[e], s1e = s1[e];
    #pragma unroll
    for (int mi = 0; mi < 2; mi++)
        #pragma unroll
        for (int nf = 0; nf < 8; nf++) {
            int r0  = tile * BM + wr * 32 + mi * 16 + (lane >> 2);
            int col = bx * 64 + wc * 32 + nf * 4 + (lane & 3);
            float g0 = acc[mi][nf][0] * s0e, u0 = acc[mi][nf][1] * s1e;
            float g8 = acc[mi][nf][2] * s0e, u8 = acc[mi][nf][3] * s1e;
            float h0 = (g0 / (1.f + __expf(-g0))) * u0;
            float h8 = (g8 / (1.f + __expf(-g8))) * u8;
            size_t o0 = (size_t)r0 * DFF_DIM + col;
            size_t o8 = o0 + (size_t)8 * DFF_DIM;
            __half b0 = __float2half_rn(h0);
            __half b8 = __float2half_rn(h8);
            g_Hhi[o0] = b0; g_Hlo[o0] = __float2half_rn(h0 - __half2float(b0));
            g_Hhi[o8] = b8; g_Hlo[o8] = __float2half_rn(h8 - __half2float(b8));
        }
}

// ---------------- GEMM2: H @ w2^T * s2 -> Y ----------------
// CTA 128 rows x 128 d-cols. Warp grid 4x2, warp tile 32x64. cp.async 3-stage.
__global__ void __launch_bounds__(256, 2) gemm2_mma(const float* __restrict__ s2)
{
    int tile = blockIdx.y;
    if (tile >= g_ntiles) return;
    int e  = g_tile_e[tile];
    int bx = blockIdx.x;

    extern __shared__ char smem[];
    uint32_t sb = smem_u32(smem);
    int tid = threadIdx.x, lane = tid & 31, wid = tid >> 5;
    int wr = wid >> 1, wc = wid & 1;

    // ---- cp.async A chunks (H fp16 hi/lo) ----
    const char* asrc[4]; uint32_t adst[4];
    #pragma unroll
    for (int i = 0; i < 4; i++) {
        int idx = i * 256 + tid;
        int pl = idx >> 9, rem = idx & 511;
        int r = rem >> 2, c = rem & 3;
        const __half* base = pl ? g_Hlo : g_Hhi;
        asrc[i] = (const char*)(base + (size_t)(tile * BM + r) * DFF_DIM + c * 8);
        adst[i] = (uint32_t)((pl ? A_LO : A_HI) + r * ROWSTRIDE + c * 16);
    }
    const char* bsrc[2]; uint32_t bdst[2];
    #pragma unroll
    for (int i = 0; i < 2; i++) {
        int idx = i * 256 + tid;
        int r = idx >> 2, c = idx & 3;
        bsrc[i] = (const char*)(g_w2h
                + (size_t)(e * D_DIM + bx * 128 + r) * DFF_DIM + c * 8);
        bdst[i] = (uint32_t)(B_HI + r * ROWSTRIDE + c * 16);
    }

    auto fill = [&](int stg, int kb) {
        uint32_t base = sb + stg * STAGE1;
        int koff = kb * 64;
        #pragma unroll
        for (int i = 0; i < 4; i++)
            CP_ASYNC16(base + adst[i], asrc[i] + koff);
        #pragma unroll
        for (int i = 0; i < 2; i++)
            CP_ASYNC16(base + bdst[i], bsrc[i] + koff);
    };

    int li = lane & 7;
    uint32_t offA = (uint32_t)((wr * 32 + ((lane >> 3) & 1) * 8 + li) * ROWSTRIDE
                               + ((lane >> 4) & 1) * 16);
    uint32_t offB = (uint32_t)((wc * 64 + ((lane >> 4) & 1) * 8 + li) * ROWSTRIDE
                               + ((lane >> 3) & 1) * 16);

    float acc[2][8][4];
    #pragma unroll
    for (int i = 0; i < 2; i++)
        #pragma unroll
        for (int j = 0; j < 8; j++)
            #pragma unroll
            for (int c = 0; c < 4; c++) acc[i][j][c] = 0.f;

    fill(0, 0); CP_COMMIT();
    fill(1, 1); CP_COMMIT();

    const int NKB = DFF_DIM / KBLK;   // 32
    int cs = 0, fs = 2;
    for (int kb = 0; kb < NKB; kb++) {
        CP_WAIT1();
        __syncthreads();
        uint32_t st = sb + cs * STAGE1;
        #pragma unroll
        for (int s = 0; s < 2; s++) {
            uint32_t Ah[2][4], Al[2][4];
            #pragma unroll
            for (int mi = 0; mi < 2; mi++) {
                LDSM4(Ah[mi], st + A_HI + offA + mi * 16 * ROWSTRIDE + s * 32);
                LDSM4(Al[mi], st + A_LO + offA + mi * 16 * ROWSTRIDE + s * 32);
            }
            #pragma unroll
            for (int njp = 0; njp < 2; njp++) {
                uint32_t Bh[2][4];
                #pragma unroll
                for (int j = 0; j < 2; j++)
                    LDSM4(Bh[j], st + B_HI + offB + (njp * 2 + j) * 16 * ROWSTRIDE + s * 32);
                #pragma unroll
                for (int mi = 0; mi < 2; mi++)
                    #pragma unroll
                    for (int j = 0; j < 2; j++) {
                        MMAH(acc[mi][njp*4 + j*2],     Ah[mi], Bh[j][0], Bh[j][1]);
                        MMAH(acc[mi][njp*4 + j*2 + 1], Ah[mi], Bh[j][2], Bh[j][3]);
                    }
                #pragma unroll
                for (int mi = 0; mi < 2; mi++)
                    #pragma unroll
                    for (int j = 0; j < 2; j++) {
                        MMAH(acc[mi][njp*4 + j*2],     Al[mi], Bh[j][0], Bh[j][1]);
                        MMAH(acc[mi][njp*4 + j*2 + 1], Al[mi], Bh[j][2], Bh[j][3]);
                    }
            }
        }
        if (kb + 2 < NKB) fill(fs, kb + 2);
        CP_COMMIT();
        cs = (cs == 2) ? 0 : cs + 1;
        fs = (fs == 2) ? 0 : fs + 1;
    }

    float s2e = s2[e];
    #pragma unroll
    for (int mi = 0; mi < 2; mi++)
        #pragma unroll
        for (int nf = 0; nf < 8; nf++) {
            int r0  = tile * BM + wr * 32 + mi * 16 + (lane >> 2);
            int col = bx * 128 + wc * 64 + nf * 8 + 2 * (lane & 3);
            float2 v0 = make_float2(acc[mi][nf][0] * s2e, acc[mi][nf][1] * s2e);
            float2 v8 = make_float2(acc[mi][nf][2] * s2e, acc[mi][nf][3] * s2e);
            *(float2*)(g_Y + (size_t)r0 * D_DIM + col) = v0;
            *(float2*)(g_Y + (size_t)(r0 + 8) * D_DIM + col) = v8;
        }
}

// ---------------- final gather: out[t] = sum_k rw[t,k] * Y[slot(t,k)] ----------------
__global__ void gather_kernel(float* __restrict__ out, const float* __restrict__ rw) {
    int idx = blockIdx.x * blockDim.x + threadIdx.x;
    int t = idx >> 9;
    int q = (idx & 511) * 4;
    float4 acc = make_float4(0.f, 0.f, 0.f, 0.f);
    #pragma unroll
    for (int k = 0; k < K_TOP; k++) {
        int p = t * K_TOP + k;
        float w = rw[p];
        const float4 v = *(const float4*)(g_Y + (size_t)g_slot[p] * D_DIM + q);
        acc.x += w * v.x; acc.y += w * v.y; acc.z += w * v.z; acc.w += w * v.w;
    }
    *(float4*)(out + (size_t)t * D_DIM + q) = acc;
}

// ---------------- launch ----------------
extern "C" void kernel_launch(void* const* d_in, const int* in_sizes, int n_in,
                              void* d_out, int out_size) {
    const float* x   = (const float*)d_in[0];
    const float* w0  = (const float*)d_in[1];
    const float* w1  = (const float*)d_in[2];
    const float* w2  = (const float*)d_in[3];
    const float* s0  = (const float*)d_in[4];
    const float* s1  = (const float*)d_in[5];
    const float* s2  = (const float*)d_in[6];
    const void*  sel = d_in[7];
    const float* rw  = (const float*)d_in[8];
    float* out = (float*)d_out;

    cudaFuncSetAttribute(gemm1_mma, cudaFuncAttributeMaxDynamicSharedMemorySize, SMEM_BYTES);
    cudaFuncSetAttribute(gemm2_mma, cudaFuncAttributeMaxDynamicSharedMemorySize, SMEM_BYTES);

    convh_kernel<<<(3 * WN4 + 255) / 256, 256>>>(w0, w1, w2);
    splitx_kernel<<<((T_TOK * D_DIM / 4) + 255) / 256, 256>>>(x);

    prep0_kernel<<<(P_PAD + 255) / 256, 256>>>(sel);
    count_kernel<<<(P_PAIR + 255) / 256, 256>>>(sel);
    setup_fill_kernel<<<1, 256>>>(sel);
    gemm1_mma<<<dim3(DFF_DIM / 64, MAX_TILES), 256, SMEM_BYTES>>>(s0, s1);
    gemm2_mma<<<dim3(D_DIM / 128, MAX_TILES), 256, SMEM_BYTES>>>(s2);
    gather_kernel<<<(T_TOK * 512) / 256, 256>>>(out, rw);
}

// round 16
// speedup vs baseline: 1.8748x; 1.0375x over previous
#include <cuda_runtime.h>
#include <cuda_fp16.h>
#include <math.h>
#include <stdint.h>

// ---------------- problem constants ----------------
#define T_TOK   1024
#define D_DIM   2048
#define DFF_DIM 1024
#define E_EXP   16
#define K_TOP   6
#define P_PAIR  (T_TOK * K_TOP)          // 6144
#define BM      128
#define P_PAD   (P_PAIR + E_EXP * BM)    // 8192
#define MAX_TILES (P_PAD / BM)           // 64
#define KBLK    32
#define WN4     ((E_EXP * DFF_DIM * D_DIM) / 4)   // 8388608 float4 per weight tensor
#define EW4     (WN4 / E_EXP)            // 524288 float4 per expert per tensor

// converter block layout inside gemm1's grid
#define XBLK    32                       // x-split blocks (flag 0)
#define EBLK    48                       // w0+w1 blocks per expert (flags 1..16)
#define W2BLK   256                      // w2 blocks (no flag)
#define CONV_BLKS (XBLK + E_EXP * EBLK + W2BLK)   // 1056
#define GEMM1_GRID (CONV_BLKS + (DFF_DIM / 64) * MAX_TILES)  // 1056 + 1024

// smem stage: A hi/lo planes (128 rows), B plane (128 rows), 80B row stride
#define ROWSTRIDE 80
#define A_HI 0
#define A_LO 10240
#define B_HI 20480
#define STAGE1 30720
#define NSTAGE 3
#define SMEM_BYTES (NSTAGE * STAGE1)     // 92160; 2 CTA/SM

// ---------------- static device scratch ----------------
__device__ int   g_rows[P_PAD];
__device__ int   g_slot[P_PAIR];
__device__ int   g_cnt [E_EXP];
__device__ int   g_cur [E_EXP];
__device__ int   g_tile_e[MAX_TILES];
__device__ int   g_ntiles;
__device__ int   g_sel64;
__device__ int   g_flag  [E_EXP + 1];    // [0]=x ready, [1+e]=w0/w1 expert e ready
__device__ int   g_segcnt[E_EXP + 1];
__device__ __half g_xhi[(size_t)T_TOK * D_DIM];
__device__ __half g_xlo[(size_t)T_TOK * D_DIM];
__device__ __half g_w0h[(size_t)E_EXP * DFF_DIM * D_DIM];
__device__ __half g_w1h[(size_t)E_EXP * DFF_DIM * D_DIM];
__device__ __half g_w2h[(size_t)E_EXP * D_DIM * DFF_DIM];
__device__ __half g_Hhi[(size_t)P_PAD * DFF_DIM];
__device__ __half g_Hlo[(size_t)P_PAD * DFF_DIM];
__device__ float  g_Y  [(size_t)P_PAD * D_DIM];

// ---------------- helpers ----------------
__device__ __forceinline__ uint32_t smem_u32(const void* p) {
    uint32_t a;
    asm("{ .reg .u64 t; cvta.to.shared.u64 t, %1; cvt.u32.u64 %0, t; }" : "=r"(a) : "l"(p));
    return a;
}

#define LDSM4(r, addr)                                                        \
    asm volatile("ldmatrix.sync.aligned.m8n8.x4.shared.b16 {%0,%1,%2,%3}, [%4];" \
        : "=r"((r)[0]), "=r"((r)[1]), "=r"((r)[2]), "=r"((r)[3]) : "r"(addr))

#define MMAH(c, a, b0, b1)                                                    \
    asm volatile("mma.sync.aligned.m16n8k16.row.col.f32.f16.f16.f32 "         \
        "{%0,%1,%2,%3}, {%4,%5,%6,%7}, {%8,%9}, {%0,%1,%2,%3};"               \
        : "+f"((c)[0]), "+f"((c)[1]), "+f"((c)[2]), "+f"((c)[3])              \
        : "r"((a)[0]), "r"((a)[1]), "r"((a)[2]), "r"((a)[3]), "r"(b0), "r"(b1))

#define CP_ASYNC16(dst, src)                                                  \
    asm volatile("cp.async.cg.shared.global [%0], [%1], 16;"                  \
        :: "r"(dst), "l"(src) : "memory")
#define CP_ASYNC16Z(dst, src, sz)                                             \
    asm volatile("cp.async.cg.shared.global [%0], [%1], 16, %2;"              \
        :: "r"(dst), "l"(src), "r"(sz) : "memory")
#define CP_COMMIT()  asm volatile("cp.async.commit_group;" ::: "memory")
#define CP_WAIT1()   asm volatile("cp.async.wait_group 1;" ::: "memory")

__device__ __forceinline__ uint32_t pack2h(float a, float b) {
    __half2 h = __floats2half2_rn(a, b);
    return *(uint32_t*)&h;
}

// ---------------- prep0: init scratch + flags + dtype detection ----------------
__global__ void prep0_kernel(const void* sel) {
    int i = blockIdx.x * blockDim.x + threadIdx.x;
    if (i < P_PAD) g_rows[i] = -1;
    if (i < E_EXP) { g_cnt[i] = 0; g_cur[i] = 0; }
    if (i < E_EXP + 1) { g_flag[i] = 0; g_segcnt[i] = 0; }
    if (blockIdx.x == 0) {
        __shared__ int bad;
        if (threadIdx.x == 0) bad = 0;
        __syncthreads();
        const int* w = (const int*)sel;
        for (int j = threadIdx.x; j < 1024; j += blockDim.x) {
            int lo = w[2 * j], hi = w[2 * j + 1];
            if (hi != 0 || (unsigned)lo >= E_EXP) atomicOr(&bad, 1);
        }
        __syncthreads();
        if (threadIdx.x == 0) g_sel64 = bad ? 0 : 1;
    }
}
__device__ __forceinline__ int load_expert(const void* sel, int p) {
    int e = g_sel64 ? (int)((const long long*)sel)[p] : ((const int*)sel)[p];
    return e & (E_EXP - 1);
}

__global__ void count_kernel(const void* __restrict__ sel) {
    int p = blockIdx.x * blockDim.x + threadIdx.x;
    if (p < P_PAIR) atomicAdd(&g_cnt[load_expert(sel, p)], 1);
}

__global__ void setup_fill_kernel(const void* __restrict__ sel) {
    __shared__ int basepad[E_EXP];
    if (threadIdx.x == 0) {
        int pos = 0;
        for (int e = 0; e < E_EXP; e++) {
            basepad[e] = pos;
            int tiles = (g_cnt[e] + BM - 1) / BM;
            for (int i = 0; i < tiles; i++) g_tile_e[pos / BM + i] = e;
            pos += tiles * BM;
        }
        g_ntiles = pos / BM;
    }
    __syncthreads();
    for (int p = threadIdx.x; p < P_PAIR; p += blockDim.x) {
        int e = load_expert(sel, p);
        int idx = basepad[e] + atomicAdd(&g_cur[e], 1);
        g_rows[idx] = p / K_TOP;
        g_slot[p] = idx;
    }
}

// ---------------- converter helpers (run inside gemm1's low-bid blocks) ----------------
__device__ __forceinline__ void conv_f4(const float* __restrict__ src,
                                        __half* __restrict__ dst,
                                        int begin, int end, int tid) {
    for (int i = begin + tid; i < end; i += 256) {
        float4 v = ((const float4*)src)[i];
        ((uint2*)dst)[i] = make_uint2(pack2h(v.x, v.y), pack2h(v.z, v.w));
    }
}
__device__ __forceinline__ void seg_arrive(int seg, int nblk) {
    __syncthreads();
    if (threadIdx.x == 0) {
        __threadfence();
        if (atomicAdd(&g_segcnt[seg], 1) == nblk - 1)
            atomicExch(&g_flag[seg], 1);
    }
}

// ---------------- GEMM1 (fused with weight/x conversion) ----------------
// Blocks [0, CONV_BLKS): converters. Blocks [CONV_BLKS, +1024): GEMM tiles.
// GEMM: CTA 128 rows x 128 interleaved n. Warp grid 4x2, warp tile 32x64.
__global__ void __launch_bounds__(256, 2) gemm1_mma(
    const float* __restrict__ x,  const float* __restrict__ w0,
    const float* __restrict__ w1, const float* __restrict__ w2,
    const float* __restrict__ s0, const float* __restrict__ s1)
{
    int gid = blockIdx.x;
    int tid = threadIdx.x;

    if (gid < CONV_BLKS) {
        if (gid < XBLK) {
            // ---- x split: fp32 -> fp16 hi + lo (exact) ----
            const int CH = (T_TOK * D_DIM / 4) / XBLK;      // 16384
            int begin = gid * CH, end = begin + CH;
            for (int i = begin + tid; i < end; i += 256) {
                float4 v = ((const float4*)x)[i];
                float f[4] = {v.x, v.y, v.z, v.w};
                uint32_t h[4], l[4];
                #pragma unroll
                for (int j = 0; j < 4; j++) {
                    __half bh = __float2half_rn(f[j]);
                    __half bl = __float2half_rn(f[j] - __half2float(bh));
                    h[j] = (uint32_t)__half_as_ushort(bh);
                    l[j] = (uint32_t)__half_as_ushort(bl);
                }
                ((uint2*)g_xhi)[i] = make_uint2(h[0] | (h[1] << 16), h[2] | (h[3] << 16));
                ((uint2*)g_xlo)[i] = make_uint2(l[0] | (l[1] << 16), l[2] | (l[3] << 16));
            }
            seg_arrive(0, XBLK);
        } else if (gid < XBLK + E_EXP * EBLK) {
            // ---- w0+w1 for one expert: 2*EW4 float4 over EBLK blocks ----
            int e  = (gid - XBLK) / EBLK;
            int lb = (gid - XBLK) % EBLK;
            const int TOT = 2 * EW4;                         // 1048576
            const int CH  = (TOT + EBLK - 1) / EBLK;         // 21846
            int begin = lb * CH, end = min(begin + CH, TOT);
            int base = e * EW4;
            if (begin < EW4) {
                int e0 = min(end, EW4);
                conv_f4(w0, g_w0h, base + begin, base + e0, tid);
            }
            if (end > EW4) {
                int b1 = max(begin, EW4) - EW4;
                conv_f4(w1, g_w1h, base + b1, base + (end - EW4), tid);
            }
            seg_arrive(1 + e, EBLK);
        } else {
            // ---- w2: full tensor, no flag (gemm2 launches after this kernel) ----
            int lb = gid - XBLK - E_EXP * EBLK;
            const int CH = WN4 / W2BLK;                      // 32768
            conv_f4(w2, g_w2h, lb * CH, (lb + 1) * CH, tid);
        }
        return;
    }

    // ---------------- GEMM block ----------------
    int g    = gid - CONV_BLKS;
    int bx   = g & 15;
    int tile = g >> 4;
    if (tile >= g_ntiles) return;
    int e = g_tile_e[tile];

    // wait for x + this expert's weights (producers have strictly lower bids)
    if (tid == 0) {
        while (atomicAdd(&g_flag[0], 0) == 0) __nanosleep(200);
        while (atomicAdd(&g_flag[1 + e], 0) == 0) __nanosleep(200);
    }
    __syncthreads();

    extern __shared__ char smem[];
    uint32_t sb = smem_u32(smem);
    int lane = tid & 31, wid = tid >> 5;
    int wr = wid >> 1, wc = wid & 1;

    // ---- cp.async A chunks: 1024 (2 planes x 128 rows x 4) ----
    const char* asrc[4]; uint32_t adst[4]; uint32_t asz[4];
    #pragma unroll
    for (int i = 0; i < 4; i++) {
        int idx = i * 256 + tid;
        int pl = idx >> 9, rem = idx & 511;
        int r = rem >> 2, c = rem & 3;
        int grow = g_rows[tile * BM + r];
        const __half* base = pl ? g_xlo : g_xhi;
        asrc[i] = (const char*)(base + (size_t)(grow < 0 ? 0 : grow) * D_DIM + c * 8);
        asz[i]  = (grow < 0) ? 0u : 16u;
        adst[i] = (uint32_t)((pl ? A_LO : A_HI) + r * ROWSTRIDE + c * 16);
    }
    // ---- cp.async B chunks: 512 (128 interleaved rows x 4) ----
    const char* bsrc[2]; uint32_t bdst[2];
    #pragma unroll
    for (int i = 0; i < 2; i++) {
        int idx = i * 256 + tid;
        int r = idx >> 2, c = idx & 3;
        int dffcol = bx * 64 + (r >> 1);
        bsrc[i] = (const char*)(((r & 1) ? g_w1h : g_w0h)
                + (size_t)(e * DFF_DIM + dffcol) * D_DIM + c * 8);
        bdst[i] = (uint32_t)(B_HI + r * ROWSTRIDE + c * 16);
    }

    auto fill = [&](int stg, int kb) {
        uint32_t base = sb + stg * STAGE1;
        int koff = kb * 64;
        #pragma unroll
        for (int i = 0; i < 4; i++)
            CP_ASYNC16Z(base + adst[i], asrc[i] + koff, asz[i]);
        #pragma unroll
        for (int i = 0; i < 2; i++)
            CP_ASYNC16(base + bdst[i], bsrc[i] + koff);
    };

    int li = lane & 7;
    uint32_t offA = (uint32_t)((wr * 32 + ((lane >> 3) & 1) * 8 + li) * ROWSTRIDE
                               + ((lane >> 4) & 1) * 16);
    uint32_t offB = (uint32_t)((wc * 64 + ((lane >> 4) & 1) * 8 + li) * ROWSTRIDE
                               + ((lane >> 3) & 1) * 16);

    float acc[2][8][4];
    #pragma unroll
    for (int i = 0; i < 2; i++)
        #pragma unroll
        for (int j = 0; j < 8; j++)
            #pragma unroll
            for (int c = 0; c < 4; c++) acc[i][j][c] = 0.f;

    fill(0, 0); CP_COMMIT();
    fill(1, 1); CP_COMMIT();

    const int NKB = D_DIM / KBLK;   // 64
    int cs = 0, fs = 2;
    for (int kb = 0; kb < NKB; kb++) {
        CP_WAIT1();
        __syncthreads();
        uint32_t st = sb + cs * STAGE1;
        #pragma unroll
        for (int s = 0; s < 2; s++) {
            uint32_t Ah[2][4], Al[2][4];
            #pragma unroll
            for (int mi = 0; mi < 2; mi++) {
                LDSM4(Ah[mi], st + A_HI + offA + mi * 16 * ROWSTRIDE + s * 32);
                LDSM4(Al[mi], st + A_LO + offA + mi * 16 * ROWSTRIDE + s * 32);
            }
            #pragma unroll
            for (int njp = 0; njp < 2; njp++) {
                uint32_t Bh[2][4];
                #pragma unroll
                for (int j = 0; j < 2; j++)
                    LDSM4(Bh[j], st + B_HI + offB + (njp * 2 + j) * 16 * ROWSTRIDE + s * 32);
                #pragma unroll
                for (int mi = 0; mi < 2; mi++)
                    #pragma unroll
                    for (int j = 0; j < 2; j++) {
                        MMAH(acc[mi][njp*4 + j*2],     Ah[mi], Bh[j][0], Bh[j][1]);
                        MMAH(acc[mi][njp*4 + j*2 + 1], Ah[mi], Bh[j][2], Bh[j][3]);
                    }
                #pragma unroll
                for (int mi = 0; mi < 2; mi++)
                    #pragma unroll
                    for (int j = 0; j < 2; j++) {
                        MMAH(acc[mi][njp*4 + j*2],     Al[mi], Bh[j][0], Bh[j][1]);
                        MMAH(acc[mi][njp*4 + j*2 + 1], Al[mi], Bh[j][2], Bh[j][3]);
                    }
            }
        }
        if (kb + 2 < NKB) fill(fs, kb + 2);
        CP_COMMIT();
        cs = (cs == 2) ? 0 : cs + 1;
        fs = (fs == 2) ? 0 : fs + 1;
    }

    // ---- epilogue: SwiGLU, store H hi/lo fp16 ----
    float s0e = s0[e], s1e = s1[e];
    #pragma unroll
    for (int mi = 0; mi < 2; mi++)
        #pragma unroll
        for (int nf = 0; nf < 8; nf++) {
            int r0  = tile * BM + wr * 32 + mi * 16 + (lane >> 2);
            int col = bx * 64 + wc * 32 + nf * 4 + (lane & 3);
            float g0 = acc[mi][nf][0] * s0e, u0 = acc[mi][nf][1] * s1e;
            float g8 = acc[mi][nf][2] * s0e, u8 = acc[mi][nf][3] * s1e;
            float h0 = (g0 / (1.f + __expf(-g0))) * u0;
            float h8 = (g8 / (1.f + __expf(-g8))) * u8;
            size_t o0 = (size_t)r0 * DFF_DIM + col;
            size_t o8 = o0 + (size_t)8 * DFF_DIM;
            __half b0 = __float2half_rn(h0);
            __half b8 = __float2half_rn(h8);
            g_Hhi[o0] = b0; g_Hlo[o0] = __float2half_rn(h0 - __half2float(b0));
            g_Hhi[o8] = b8; g_Hlo[o8] = __float2half_rn(h8 - __half2float(b8));
        }
}

// ---------------- GEMM2: H @ w2^T * s2 -> Y ----------------
__global__ void __launch_bounds__(256, 2) gemm2_mma(const float* __restrict__ s2)
{
    int tile = blockIdx.y;
    if (tile >= g_ntiles) return;
    int e  = g_tile_e[tile];
    int bx = blockIdx.x;

    extern __shared__ char smem[];
    uint32_t sb = smem_u32(smem);
    int tid = threadIdx.x, lane = tid & 31, wid = tid >> 5;
    int wr = wid >> 1, wc = wid & 1;

    const char* asrc[4]; uint32_t adst[4];
    #pragma unroll
    for (int i = 0; i < 4; i++) {
        int idx = i * 256 + tid;
        int pl = idx >> 9, rem = idx & 511;
        int r = rem >> 2, c = rem & 3;
        const __half* base = pl ? g_Hlo : g_Hhi;
        asrc[i] = (const char*)(base + (size_t)(tile * BM + r) * DFF_DIM + c * 8);
        adst[i] = (uint32_t)((pl ? A_LO : A_HI) + r * ROWSTRIDE + c * 16);
    }
    const char* bsrc[2]; uint32_t bdst[2];
    #pragma unroll
    for (int i = 0; i < 2; i++) {
        int idx = i * 256 + tid;
        int r = idx >> 2, c = idx & 3;
        bsrc[i] = (const char*)(g_w2h
                + (size_t)(e * D_DIM + bx * 128 + r) * DFF_DIM + c * 8);
        bdst[i] = (uint32_t)(B_HI + r * ROWSTRIDE + c * 16);
    }

    auto fill = [&](int stg, int kb) {
        uint32_t base = sb + stg * STAGE1;
        int koff = kb * 64;
        #pragma unroll
        for (int i = 0; i < 4; i++)
            CP_ASYNC16(base + adst[i], asrc[i] + koff);
        #pragma unroll
        for (int i = 0; i < 2; i++)
            CP_ASYNC16(base + bdst[i], bsrc[i] + koff);
    };

    int li = lane & 7;
    uint32_t offA = (uint32_t)((wr * 32 + ((lane >> 3) & 1) * 8 + li) * ROWSTRIDE
                               + ((lane >> 4) & 1) * 16);
    uint32_t offB = (uint32_t)((wc * 64 + ((lane >> 4) & 1) * 8 + li) * ROWSTRIDE
                               + ((lane >> 3) & 1) * 16);

    float acc[2][8][4];
    #pragma unroll
    for (int i = 0; i < 2; i++)
        #pragma unroll
        for (int j = 0; j < 8; j++)
            #pragma unroll
            for (int c = 0; c < 4; c++) acc[i][j][c] = 0.f;

    fill(0, 0); CP_COMMIT();
    fill(1, 1); CP_COMMIT();

    const int NKB = DFF_DIM / KBLK;   // 32
    int cs = 0, fs = 2;
    for (int kb = 0; kb < NKB; kb++) {
        CP_WAIT1();
        __syncthreads();
        uint32_t st = sb + cs * STAGE1;
        #pragma unroll
        for (int s = 0; s < 2; s++) {
            uint32_t Ah[2][4], Al[2][4];
            #pragma unroll
            for (int mi = 0; mi < 2; mi++) {
                LDSM4(Ah[mi], st + A_HI + offA + mi * 16 * ROWSTRIDE + s * 32);
                LDSM4(Al[mi], st + A_LO + offA + mi * 16 * ROWSTRIDE + s * 32);
            }
            #pragma unroll
            for (int njp = 0; njp < 2; njp++) {
                uint32_t Bh[2][4];
                #pragma unroll
                for (int j = 0; j < 2; j++)
                    LDSM4(Bh[j], st + B_HI + offB + (njp * 2 + j) * 16 * ROWSTRIDE + s * 32);
                #pragma unroll
                for (int mi = 0; mi < 2; mi++)
                    #pragma unroll
                    for (int j = 0; j < 2; j++) {
                        MMAH(acc[mi][njp*4 + j*2],     Ah[mi], Bh[j][0], Bh[j][1]);
                        MMAH(acc[mi][njp*4 + j*2 + 1], Ah[mi], Bh[j][2], Bh[j][3]);
                    }
                #pragma unroll
                for (int mi = 0; mi < 2; mi++)
                    #pragma unroll
                    for (int j = 0; j < 2; j++) {
                        MMAH(acc[mi][njp*4 + j*2],     Al[mi], Bh[j][0], Bh[j][1]);
                        MMAH(acc[mi][njp*4 + j*2 + 1], Al[mi], Bh[j][2], Bh[j][3]);
                    }
            }
        }
        if (kb + 2 < NKB) fill(fs, kb + 2);
        CP_COMMIT();
        cs = (cs == 2) ? 0 : cs + 1;
        fs = (fs == 2) ? 0 : fs + 1;
    }

    float s2e = s2[e];
    #pragma unroll
    for (int mi = 0; mi < 2; mi++)
        #pragma unroll
        for (int nf = 0; nf < 8; nf++) {
            int r0  = tile * BM + wr * 32 + mi * 16 + (lane >> 2);
            int col = bx * 128 + wc * 64 + nf * 8 + 2 * (lane & 3);
            float2 v0 = make_float2(acc[mi][nf][0] * s2e, acc[mi][nf][1] * s2e);
            float2 v8 = make_float2(acc[mi][nf][2] * s2e, acc[mi][nf][3] * s2e);
            *(float2*)(g_Y + (size_t)r0 * D_DIM + col) = v0;
            *(float2*)(g_Y + (size_t)(r0 + 8) * D_DIM + col) = v8;
        }
}

// ---------------- final gather: out[t] = sum_k rw[t,k] * Y[slot(t,k)] ----------------
__global__ void gather_kernel(float* __restrict__ out, const float* __restrict__ rw) {
    int idx = blockIdx.x * blockDim.x + threadIdx.x;
    int t = idx >> 9;
    int q = (idx & 511) * 4;
    float4 acc = make_float4(0.f, 0.f, 0.f, 0.f);
    #pragma unroll
    for (int k = 0; k < K_TOP; k++) {
        int p = t * K_TOP + k;
        float w = rw[p];
        const float4 v = *(const float4*)(g_Y + (size_t)g_slot[p] * D_DIM + q);
        acc.x += w * v.x; acc.y += w * v.y; acc.z += w * v.z; acc.w += w * v.w;
    }
    *(float4*)(out + (size_t)t * D_DIM + q) = acc;
}

// ---------------- launch ----------------
extern "C" void kernel_launch(void* const* d_in, const int* in_sizes, int n_in,
                              void* d_out, int out_size) {
    const float* x   = (const float*)d_in[0];
    const float* w0  = (const float*)d_in[1];
    const float* w1  = (const float*)d_in[2];
    const float* w2  = (const float*)d_in[3];
    const float* s0  = (const float*)d_in[4];
    const float* s1  = (const float*)d_in[5];
    const float* s2  = (const float*)d_in[6];
    const void*  sel = d_in[7];
    const float* rw  = (const float*)d_in[8];
    float* out = (float*)d_out;

    cudaFuncSetAttribute(gemm1_mma, cudaFuncAttributeMaxDynamicSharedMemorySize, SMEM_BYTES);
    cudaFuncSetAttribute(gemm2_mma, cudaFuncAttributeMaxDynamicSharedMemorySize, SMEM_BYTES);

    prep0_kernel<<<(P_PAD + 255) / 256, 256>>>(sel);
    count_kernel<<<(P_PAIR + 255) / 256, 256>>>(sel);
    setup_fill_kernel<<<1, 256>>>(sel);
    // fused: converter blocks (bids 0..1055) + GEMM tiles (bids 1056..2079)
    gemm1_mma<<<GEMM1_GRID, 256, SMEM_BYTES>>>(x, w0, w1, w2, s0, s1);
    gemm2_mma<<<dim3(D_DIM / 128, MAX_TILES), 256, SMEM_BYTES>>>(s2);
    gather_kernel<<<(T_TOK * 512) / 256, 256>>>(out, rw);
}

// round 17
// speedup vs baseline: 2.7337x; 1.4581x over previous
#include <cuda_runtime.h>
#include <cuda_fp16.h>
#include <math.h>
#include <stdint.h>

// ---------------- problem constants ----------------
#define T_TOK   1024
#define D_DIM   2048
#define DFF_DIM 1024
#define E_EXP   16
#define K_TOP   6
#define P_PAIR  (T_TOK * K_TOP)          // 6144
#define BM      128
#define P_PAD   (P_PAIR + E_EXP * BM)    // 8192
#define MAX_TILES (P_PAD / BM)           // 64
#define KBLK    32
#define WN4     ((E_EXP * DFF_DIM * D_DIM) / 4)
#define EW4     (WN4 / E_EXP)            // 524288 float4 per expert per tensor

// fused grid layout: converters | gemm1 tiles | gemm2 tiles
#define XBLK    32                       // x convert (flag 0)
#define EBLK    48                       // w0+w1 per expert (flags 1..16)
#define W2E     16                       // w2 blocks per expert (flags 17..32)
#define CONV_BLKS (XBLK + E_EXP * EBLK + E_EXP * W2E)   // 1056
#define G1_BLKS ((DFF_DIM / 64) * MAX_TILES)            // 1024
#define G2_BLKS ((D_DIM / 128) * MAX_TILES)             // 1024
#define GRID_ALL (CONV_BLKS + G1_BLKS + G2_BLKS)        // 3104
#define NFLAGS  (33 + MAX_TILES)         // 97: x, w01[16], w2[16], Htile[64]

// smem stage: A plane (128 rows) + B plane (128 rows), 80B row stride
#define ROWSTRIDE 80
#define A_HI 0
#define B_HI 10240
#define STAGE1 20480
#define NSTAGE 4
#define SMEM_BYTES (NSTAGE * STAGE1)     // 81920; 2 CTA/SM -> 163.8KB

// ---------------- static device scratch ----------------
__device__ int   g_rows[P_PAD];
__device__ int   g_slot[P_PAIR];
__device__ int   g_cnt [E_EXP];
__device__ int   g_cur [E_EXP];
__device__ int   g_tile_e[MAX_TILES];
__device__ int   g_ntiles;
__device__ int   g_sel64;
__device__ int   g_flag  [NFLAGS];
__device__ int   g_segcnt[NFLAGS];
__device__ __half g_xh [(size_t)T_TOK * D_DIM];            // 4 MB
__device__ __half g_w0h[(size_t)E_EXP * DFF_DIM * D_DIM];  // 64 MB
__device__ __half g_w1h[(size_t)E_EXP * DFF_DIM * D_DIM];  // 64 MB
__device__ __half g_w2h[(size_t)E_EXP * D_DIM * DFF_DIM];  // 64 MB
__device__ __half g_Hh [(size_t)P_PAD * DFF_DIM];          // 16 MB
__device__ float  g_Y  [(size_t)P_PAD * D_DIM];            // 64 MB

// ---------------- helpers ----------------
__device__ __forceinline__ uint32_t smem_u32(const void* p) {
    uint32_t a;
    asm("{ .reg .u64 t; cvta.to.shared.u64 t, %1; cvt.u32.u64 %0, t; }" : "=r"(a) : "l"(p));
    return a;
}

#define LDSM4(r, addr)                                                        \
    asm volatile("ldmatrix.sync.aligned.m8n8.x4.shared.b16 {%0,%1,%2,%3}, [%4];" \
        : "=r"((r)[0]), "=r"((r)[1]), "=r"((r)[2]), "=r"((r)[3]) : "r"(addr))

#define MMAH(c, a, b0, b1)                                                    \
    asm volatile("mma.sync.aligned.m16n8k16.row.col.f32.f16.f16.f32 "         \
        "{%0,%1,%2,%3}, {%4,%5,%6,%7}, {%8,%9}, {%0,%1,%2,%3};"               \
        : "+f"((c)[0]), "+f"((c)[1]), "+f"((c)[2]), "+f"((c)[3])              \
        : "r"((a)[0]), "r"((a)[1]), "r"((a)[2]), "r"((a)[3]), "r"(b0), "r"(b1))

#define CP_ASYNC16(dst, src)                                                  \
    asm volatile("cp.async.cg.shared.global [%0], [%1], 16;"                  \
        :: "r"(dst), "l"(src) : "memory")
#define CP_ASYNC16Z(dst, src, sz)                                             \
    asm volatile("cp.async.cg.shared.global [%0], [%1], 16, %2;"              \
        :: "r"(dst), "l"(src), "r"(sz) : "memory")
#define CP_COMMIT()  asm volatile("cp.async.commit_group;" ::: "memory")
#define CP_WAIT2()   asm volatile("cp.async.wait_group 2;" ::: "memory")

__device__ __forceinline__ uint32_t pack2h(float a, float b) {
    __half2 h = __floats2half2_rn(a, b);
    return *(uint32_t*)&h;
}

// ---------------- prep0: init scratch + flags + dtype detection ----------------
__global__ void prep0_kernel(const void* sel) {
    int i = blockIdx.x * blockDim.x + threadIdx.x;
    if (i < P_PAD) g_rows[i] = -1;
    if (i < E_EXP) { g_cnt[i] = 0; g_cur[i] = 0; }
    if (i < NFLAGS) { g_flag[i] = 0; g_segcnt[i] = 0; }
    if (blockIdx.x == 0) {
        __shared__ int bad;
        if (threadIdx.x == 0) bad = 0;
        __syncthreads();
        const int* w = (const int*)sel;
        for (int j = threadIdx.x; j < 1024; j += blockDim.x) {
            int lo = w[2 * j], hi = w[2 * j + 1];
            if (hi != 0 || (unsigned)lo >= E_EXP) atomicOr(&bad, 1);
        }
        __syncthreads();
        if (threadIdx.x == 0) g_sel64 = bad ? 0 : 1;
    }
}
__device__ __forceinline__ int load_expert(const void* sel, int p) {
    int e = g_sel64 ? (int)((const long long*)sel)[p] : ((const int*)sel)[p];
    return e & (E_EXP - 1);
}

__global__ void count_kernel(const void* __restrict__ sel) {
    int p = blockIdx.x * blockDim.x + threadIdx.x;
    if (p < P_PAIR) atomicAdd(&g_cnt[load_expert(sel, p)], 1);
}

__global__ void setup_fill_kernel(const void* __restrict__ sel) {
    __shared__ int basepad[E_EXP];
    if (threadIdx.x == 0) {
        int pos = 0;
        for (int e = 0; e < E_EXP; e++) {
            basepad[e] = pos;
            int tiles = (g_cnt[e] + BM - 1) / BM;
            for (int i = 0; i < tiles; i++) g_tile_e[pos / BM + i] = e;
            pos += tiles * BM;
        }
        g_ntiles = pos / BM;
    }
    __syncthreads();
    for (int p = threadIdx.x; p < P_PAIR; p += blockDim.x) {
        int e = load_expert(sel, p);
        int idx = basepad[e] + atomicAdd(&g_cur[e], 1);
        g_rows[idx] = p / K_TOP;
        g_slot[p] = idx;
    }
}

// ---------------- converter helpers ----------------
__device__ __forceinline__ void conv_f4(const float* __restrict__ src,
                                        __half* __restrict__ dst,
                                        int begin, int end, int tid) {
    for (int i = begin + tid; i < end; i += 256) {
        float4 v = ((const float4*)src)[i];
        ((uint2*)dst)[i] = make_uint2(pack2h(v.x, v.y), pack2h(v.z, v.w));
    }
}
__device__ __forceinline__ void seg_arrive(int seg, int nblk) {
    __syncthreads();
    if (threadIdx.x == 0) {
        __threadfence();
        if (atomicAdd(&g_segcnt[seg], 1) == nblk - 1)
            atomicExch(&g_flag[seg], 1);
    }
}
__device__ __forceinline__ void wait_flag(int seg) {
    if (threadIdx.x == 0)
        while (atomicAdd(&g_flag[seg], 0) == 0) __nanosleep(200);
    __syncthreads();
}

// ---------------- mega kernel: converters + gemm1 + gemm2 ----------------
// bids [0,1056): converters; [1056,2080): gemm1 tiles; [2080,3104): gemm2 tiles.
// Both GEMMs: CTA 128x128, warp grid 4x2, warp tile 32x64, single-pass fp16.
__global__ void __launch_bounds__(256, 2) mega_mma(
    const float* __restrict__ x,  const float* __restrict__ w0,
    const float* __restrict__ w1, const float* __restrict__ w2,
    const float* __restrict__ s0, const float* __restrict__ s1,
    const float* __restrict__ s2)
{
    int gid = blockIdx.x;
    int tid = threadIdx.x;

    if (gid < CONV_BLKS) {
        if (gid < XBLK) {
            const int CH = (T_TOK * D_DIM / 4) / XBLK;
            conv_f4(x, g_xh, gid * CH, (gid + 1) * CH, tid);
            seg_arrive(0, XBLK);
        } else if (gid < XBLK + E_EXP * EBLK) {
            int e  = (gid - XBLK) / EBLK;
            int lb = (gid - XBLK) % EBLK;
            const int TOT = 2 * EW4;
            const int CH  = (TOT + EBLK - 1) / EBLK;
            int begin = lb * CH, end = min(begin + CH, TOT);
            int base = e * EW4;
            if (begin < EW4)
                conv_f4(w0, g_w0h, base + begin, base + min(end, EW4), tid);
            if (end > EW4)
                conv_f4(w1, g_w1h, base + max(begin, EW4) - EW4, base + (end - EW4), tid);
            seg_arrive(1 + e, EBLK);
        } else {
            int lb = gid - XBLK - E_EXP * EBLK;     // 0..255
            int e = lb >> 4, sub = lb & 15;
            const int CH = EW4 / W2E;               // 32768
            int begin = e * EW4 + sub * CH;
            conv_f4(w2, g_w2h, begin, begin + CH, tid);
            seg_arrive(17 + e, W2E);
        }
        return;
    }

    extern __shared__ char smem[];
    uint32_t sb = smem_u32(smem);
    int lane = tid & 31, wid = tid >> 5;
    int wr = wid >> 1, wc = wid & 1;
    int li = lane & 7;
    uint32_t offA = (uint32_t)((wr * 32 + ((lane >> 3) & 1) * 8 + li) * ROWSTRIDE
                               + ((lane >> 4) & 1) * 16);
    uint32_t offB = (uint32_t)((wc * 64 + ((lane >> 4) & 1) * 8 + li) * ROWSTRIDE
                               + ((lane >> 3) & 1) * 16);

    float acc[2][8][4];
    #pragma unroll
    for (int i = 0; i < 2; i++)
        #pragma unroll
        for (int j = 0; j < 8; j++)
            #pragma unroll
            for (int c = 0; c < 4; c++) acc[i][j][c] = 0.f;

    if (gid < CONV_BLKS + G1_BLKS) {
        // ---------------- GEMM1 tile ----------------
        int g    = gid - CONV_BLKS;
        int bx   = g & 15;
        int tile = g >> 4;
        if (tile >= g_ntiles) return;
        int e = g_tile_e[tile];

        wait_flag(0);
        wait_flag(1 + e);

        // A chunks: 512 (128 rows x 4), 2 per thread
        const char* asrc[2]; uint32_t adst[2]; uint32_t asz[2];
        #pragma unroll
        for (int i = 0; i < 2; i++) {
            int idx = i * 256 + tid;
            int r = idx >> 2, c = idx & 3;
            int grow = g_rows[tile * BM + r];
            asrc[i] = (const char*)(g_xh + (size_t)(grow < 0 ? 0 : grow) * D_DIM + c * 8);
            asz[i]  = (grow < 0) ? 0u : 16u;
            adst[i] = (uint32_t)(A_HI + r * ROWSTRIDE + c * 16);
        }
        // B chunks: 512 (128 interleaved rows x 4), 2 per thread
        const char* bsrc[2]; uint32_t bdst[2];
        #pragma unroll
        for (int i = 0; i < 2; i++) {
            int idx = i * 256 + tid;
            int r = idx >> 2, c = idx & 3;
            int dffcol = bx * 64 + (r >> 1);
            bsrc[i] = (const char*)(((r & 1) ? g_w1h : g_w0h)
                    + (size_t)(e * DFF_DIM + dffcol) * D_DIM + c * 8);
            bdst[i] = (uint32_t)(B_HI + r * ROWSTRIDE + c * 16);
        }
        auto fill = [&](int stg, int kb) {
            uint32_t base = sb + stg * STAGE1;
            int koff = kb * 64;
            #pragma unroll
            for (int i = 0; i < 2; i++)
                CP_ASYNC16Z(base + adst[i], asrc[i] + koff, asz[i]);
            #pragma unroll
            for (int i = 0; i < 2; i++)
                CP_ASYNC16(base + bdst[i], bsrc[i] + koff);
        };

        fill(0, 0); CP_COMMIT();
        fill(1, 1); CP_COMMIT();
        fill(2, 2); CP_COMMIT();

        const int NKB = D_DIM / KBLK;   // 64
        int cs = 0, fs = 3;
        for (int kb = 0; kb < NKB; kb++) {
            CP_WAIT2();
            __syncthreads();
            uint32_t st = sb + cs * STAGE1;
            #pragma unroll
            for (int s = 0; s < 2; s++) {
                uint32_t Ah[2][4];
                #pragma unroll
                for (int mi = 0; mi < 2; mi++)
                    LDSM4(Ah[mi], st + A_HI + offA + mi * 16 * ROWSTRIDE + s * 32);
                #pragma unroll
                for (int njp = 0; njp < 2; njp++) {
                    uint32_t Bh[2][4];
                    #pragma unroll
                    for (int j = 0; j < 2; j++)
                        LDSM4(Bh[j], st + B_HI + offB + (njp * 2 + j) * 16 * ROWSTRIDE + s * 32);
                    #pragma unroll
                    for (int mi = 0; mi < 2; mi++)
                        #pragma unroll
                        for (int j = 0; j < 2; j++) {
                            MMAH(acc[mi][njp*4 + j*2],     Ah[mi], Bh[j][0], Bh[j][1]);
                            MMAH(acc[mi][njp*4 + j*2 + 1], Ah[mi], Bh[j][2], Bh[j][3]);
                        }
                }
            }
            if (kb + 3 < NKB) fill(fs, kb + 3);
            CP_COMMIT();
            cs = (cs + 1) & 3;
            fs = (fs + 1) & 3;
        }

        // epilogue: SwiGLU, store H fp16
        float s0e = s0[e], s1e = s1[e];
        #pragma unroll
        for (int mi = 0; mi < 2; mi++)
            #pragma unroll
            for (int nf = 0; nf < 8; nf++) {
                int r0  = tile * BM + wr * 32 + mi * 16 + (lane >> 2);
                int col = bx * 64 + wc * 32 + nf * 4 + (lane & 3);
                float g0 = acc[mi][nf][0] * s0e, u0 = acc[mi][nf][1] * s1e;
                float g8 = acc[mi][nf][2] * s0e, u8 = acc[mi][nf][3] * s1e;
                float h0 = (g0 / (1.f + __expf(-g0))) * u0;
                float h8 = (g8 / (1.f + __expf(-g8))) * u8;
                size_t o0 = (size_t)r0 * DFF_DIM + col;
                g_Hh[o0] = __float2half_rn(h0);
                g_Hh[o0 + (size_t)8 * DFF_DIM] = __float2half_rn(h8);
            }
        // signal this tile's H complete (16 bx blocks per tile)
        seg_arrive(33 + tile, 16);
        return;
    }

    // ---------------- GEMM2 tile ----------------
    {
        int g    = gid - CONV_BLKS - G1_BLKS;
        int bx   = g & 15;
        int tile = g >> 4;
        if (tile >= g_ntiles) return;
        int e = g_tile_e[tile];

        wait_flag(17 + e);       // w2 expert slice converted
        wait_flag(33 + tile);    // H tile ready

        const char* asrc[2]; uint32_t adst[2];
        #pragma unroll
        for (int i = 0; i < 2; i++) {
            int idx = i * 256 + tid;
            int r = idx >> 2, c = idx & 3;
            asrc[i] = (const char*)(g_Hh + (size_t)(tile * BM + r) * DFF_DIM + c * 8);
            adst[i] = (uint32_t)(A_HI + r * ROWSTRIDE + c * 16);
        }
        const char* bsrc[2]; uint32_t bdst[2];
        #pragma unroll
        for (int i = 0; i < 2; i++) {
            int idx = i * 256 + tid;
            int r = idx >> 2, c = idx & 3;
            bsrc[i] = (const char*)(g_w2h
                    + (size_t)(e * D_DIM + bx * 128 + r) * DFF_DIM + c * 8);
            bdst[i] = (uint32_t)(B_HI + r * ROWSTRIDE + c * 16);
        }
        auto fill = [&](int stg, int kb) {
            uint32_t base = sb + stg * STAGE1;
            int koff = kb * 64;
            #pragma unroll
            for (int i = 0; i < 2; i++)
                CP_ASYNC16(base + adst[i], asrc[i] + koff);
            #pragma unroll
            for (int i = 0; i < 2; i++)
                CP_ASYNC16(base + bdst[i], bsrc[i] + koff);
        };

        fill(0, 0); CP_COMMIT();
        fill(1, 1); CP_COMMIT();
        fill(2, 2); CP_COMMIT();

        const int NKB = DFF_DIM / KBLK;   // 32
        int cs = 0, fs = 3;
        for (int kb = 0; kb < NKB; kb++) {
            CP_WAIT2();
            __syncthreads();
            uint32_t st = sb + cs * STAGE1;
            #pragma unroll
            for (int s = 0; s < 2; s++) {
                uint32_t Ah[2][4];
                #pragma unroll
                for (int mi = 0; mi < 2; mi++)
                    LDSM4(Ah[mi], st + A_HI + offA + mi * 16 * ROWSTRIDE + s * 32);
                #pragma unroll
                for (int njp = 0; njp < 2; njp++) {
                    uint32_t Bh[2][4];
                    #pragma unroll
                    for (int j = 0; j < 2; j++)
                        LDSM4(Bh[j], st + B_HI + offB + (njp * 2 + j) * 16 * ROWSTRIDE + s * 32);
                    #pragma unroll
                    for (int mi = 0; mi < 2; mi++)
                        #pragma unroll
                        for (int j = 0; j < 2; j++) {
                            MMAH(acc[mi][njp*4 + j*2],     Ah[mi], Bh[j][0], Bh[j][1]);
                            MMAH(acc[mi][njp*4 + j*2 + 1], Ah[mi], Bh[j][2], Bh[j][3]);
                        }
                }
            }
            if (kb + 3 < NKB) fill(fs, kb + 3);
            CP_COMMIT();
            cs = (cs + 1) & 3;
            fs = (fs + 1) & 3;
        }

        float s2e = s2[e];
        #pragma unroll
        for (int mi = 0; mi < 2; mi++)
            #pragma unroll
            for (int nf = 0; nf < 8; nf++) {
                int r0  = tile * BM + wr * 32 + mi * 16 + (lane >> 2);
                int col = bx * 128 + wc * 64 + nf * 8 + 2 * (lane & 3);
                float2 v0 = make_float2(acc[mi][nf][0] * s2e, acc[mi][nf][1] * s2e);
                float2 v8 = make_float2(acc[mi][nf][2] * s2e, acc[mi][nf][3] * s2e);
                *(float2*)(g_Y + (size_t)r0 * D_DIM + col) = v0;
                *(float2*)(g_Y + (size_t)(r0 + 8) * D_DIM + col) = v8;
            }
    }
}

// ---------------- final gather: out[t] = sum_k rw[t,k] * Y[slot(t,k)] ----------------
__global__ void gather_kernel(float* __restrict__ out, const float* __restrict__ rw) {
    int idx = blockIdx.x * blockDim.x + threadIdx.x;
    int t = idx >> 9;
    int q = (idx & 511) * 4;
    float4 acc = make_float4(0.f, 0.f, 0.f, 0.f);
    #pragma unroll
    for (int k = 0; k < K_TOP; k++) {
        int p = t * K_TOP + k;
        float w = rw[p];
        const float4 v = *(const float4*)(g_Y + (size_t)g_slot[p] * D_DIM + q);
        acc.x += w * v.x; acc.y += w * v.y; acc.z += w * v.z; acc.w += w * v.w;
    }
    *(float4*)(out + (size_t)t * D_DIM + q) = acc;
}

// ---------------- launch ----------------
extern "C" void kernel_launch(void* const* d_in, const int* in_sizes, int n_in,
                              void* d_out, int out_size) {
    const float* x   = (const float*)d_in[0];
    const float* w0  = (const float*)d_in[1];
    const float* w1  = (const float*)d_in[2];
    const float* w2  = (const float*)d_in[3];
    const float* s0  = (const float*)d_in[4];
    const float* s1  = (const float*)d_in[5];
    const float* s2  = (const float*)d_in[6];
    const void*  sel = d_in[7];
    const float* rw  = (const float*)d_in[8];
    float* out = (float*)d_out;

    cudaFuncSetAttribute(mega_mma, cudaFuncAttributeMaxDynamicSharedMemorySize, SMEM_BYTES);

    prep0_kernel<<<(P_PAD + 255) / 256, 256>>>(sel);
    count_kernel<<<(P_PAIR + 255) / 256, 256>>>(sel);
    setup_fill_kernel<<<1, 256>>>(sel);
    mega_mma<<<GRID_ALL, 256, SMEM_BYTES>>>(x, w0, w1, w2, s0, s1, s2);
    gather_kernel<<<(T_TOK * 512) / 256, 256>>>(out, rw);
}